// round 1
// baseline (speedup 1.0000x reference)
#include <cuda_runtime.h>

#define BB 16384
#define DD 64
#define LCAT 8
#define LTXT 64
#define NTOPIN 79
#define NT1 128
#define NT2 64

// Transposed intermediate: xT[k][s], k in [0,79), s in [0,B)
__device__ float g_xT[NTOPIN * BB];

// ---------------------------------------------------------------------------
// Kernel 1: warp-per-sample. Gathers, mean-bags, bottom MLP, projection,
// pairwise interactions. Writes xT (transposed) for kernel 2.
// Each lane owns dims (2*lane, 2*lane+1) as a float2.
// ---------------------------------------------------------------------------
__global__ __launch_bounds__(256) void feat_kernel(
    const int* __restrict__ user, const int* __restrict__ item,
    const int* __restrict__ brand, const int* __restrict__ cat_idx,
    const int* __restrict__ cat_len, const int* __restrict__ text_idx,
    const int* __restrict__ text_len, const float* __restrict__ sales_rank,
    const float* __restrict__ user_tab, const float* __restrict__ item_tab,
    const float* __restrict__ brand_tab, const float* __restrict__ cat_tab,
    const float* __restrict__ text_tab,
    const float* __restrict__ W_bot, const float* __restrict__ b_bot,
    const float* __restrict__ W_proj, const float* __restrict__ b_proj)
{
    const unsigned FULL = 0xFFFFFFFFu;
    int gwarp = (blockIdx.x * blockDim.x + threadIdx.x) >> 5;
    int lane  = threadIdx.x & 31;
    if (gwarp >= BB) return;
    const int s = gwarp;

    const float2* ut = (const float2*)user_tab;
    const float2* it = (const float2*)item_tab;
    const float2* bt = (const float2*)brand_tab;
    const float2* ct = (const float2*)cat_tab;
    const float2* tt = (const float2*)text_tab;

    // ---- single-row gathers ----
    int ui = user[s];
    int ii = item[s];
    int bi = brand[s];
    float2 fu = ut[(size_t)ui * 32 + lane];
    float2 fi = it[(size_t)ii * 32 + lane];
    float2 fb = bt[(size_t)bi * 32 + lane];

    // ---- cat mean bag (len in [0,8]) ----
    int clen = cat_len[s];
    int creg = (lane < LCAT) ? cat_idx[s * LCAT + lane] : 0;
    float2 cv = make_float2(0.f, 0.f);
    for (int i = 0; i < clen; i++) {
        int idx = __shfl_sync(FULL, creg, i);
        float2 r = ct[(size_t)idx * 32 + lane];
        cv.x += r.x; cv.y += r.y;
    }
    {
        float inv = 1.f / (float)max(clen, 1);
        cv.x *= inv; cv.y *= inv;
    }

    // ---- text mean bag (len in [1,64]) ----
    int tlen = text_len[s];
    int t0 = text_idx[s * LTXT + lane];
    int t1 = text_idx[s * LTXT + 32 + lane];
    float2 tv = make_float2(0.f, 0.f);
    float2 tv2 = make_float2(0.f, 0.f);
    int i = 0;
    #pragma unroll 4
    for (; i + 1 < tlen; i += 2) {
        int ia = __shfl_sync(FULL, (i < 32) ? t0 : t1, i & 31);
        int j = i + 1;
        int ib = __shfl_sync(FULL, (j < 32) ? t0 : t1, j & 31);
        float2 ra = tt[(size_t)ia * 32 + lane];
        float2 rb = tt[(size_t)ib * 32 + lane];
        tv.x += ra.x;  tv.y += ra.y;
        tv2.x += rb.x; tv2.y += rb.y;
    }
    if (i < tlen) {
        int ia = __shfl_sync(FULL, (i < 32) ? t0 : t1, i & 31);
        float2 ra = tt[(size_t)ia * 32 + lane];
        tv.x += ra.x; tv.y += ra.y;
    }
    {
        float inv = 1.f / (float)max(tlen, 1);
        tv.x = (tv.x + tv2.x) * inv;
        tv.y = (tv.y + tv2.y) * inv;
    }

    // ---- bottom MLP: dense = relu(sr * W_bot + b_bot), 64 wide ----
    float sr = sales_rank[s];
    float d0 = fmaxf(fmaf(sr, W_bot[2 * lane],     b_bot[2 * lane]),     0.f);
    float d1 = fmaxf(fmaf(sr, W_bot[2 * lane + 1], b_bot[2 * lane + 1]), 0.f);

    // ---- projection: dense_use = dense @ W_proj + b_proj ----
    const float2* wp = (const float2*)W_proj;
    float2 du = make_float2(b_proj[2 * lane], b_proj[2 * lane + 1]);
    #pragma unroll
    for (int k = 0; k < DD; k++) {
        float dk = __shfl_sync(FULL, (k & 1) ? d1 : d0, k >> 1);
        float2 w = wp[k * 32 + lane];
        du.x = fmaf(dk, w.x, du.x);
        du.y = fmaf(dk, w.y, du.y);
    }

    // ---- pairwise interactions (15 upper-tri pairs of 6 features) ----
    float2 f[6];
    f[0] = fu; f[1] = fi; f[2] = fb; f[3] = cv; f[4] = tv; f[5] = du;

    float keep = 0.f;
    int p = 0;
    #pragma unroll
    for (int a = 0; a < 6; a++) {
        #pragma unroll
        for (int b = a + 1; b < 6; b++) {
            float dv = f[a].x * f[b].x + f[a].y * f[b].y;
            #pragma unroll
            for (int off = 16; off > 0; off >>= 1)
                dv += __shfl_xor_sync(FULL, dv, off);
            if (lane == p) keep = dv;
            p++;
        }
    }

    // ---- write transposed x: [inter(15); dense(64)] ----
    if (lane < 15) g_xT[lane * BB + s] = keep;
    g_xT[(15 + 2 * lane) * BB + s] = d0;
    g_xT[(16 + 2 * lane) * BB + s] = d1;
}

// ---------------------------------------------------------------------------
// Kernel 2: top MLP. Lane-per-sample. Weights staged in shared once per block;
// W1 transposed in smem so inner loops use float4 broadcast LDS.
// Fuses layer1 -> layer2 accumulation to avoid a 128-reg h1 array.
// ---------------------------------------------------------------------------
// smem layout (floats):
//   sW1t : 128*80  (W1 transposed, [j][k], padded k=79 zeroed)
//   sb1  : 128
//   sW2  : 128*64  ([j][m])
//   sb2  : 64
//   sW3  : 64
//   sb3  : 1
#define S_W1T 0
#define S_B1  (128 * 80)
#define S_W2  (S_B1 + 128)
#define S_B2  (S_W2 + 128 * 64)
#define S_W3  (S_B2 + 64)
#define S_B3  (S_W3 + 64)
#define S_TOT (S_B3 + 1)

__global__ __launch_bounds__(128) void top_kernel(
    const float* __restrict__ W1, const float* __restrict__ b1,
    const float* __restrict__ W2, const float* __restrict__ b2,
    const float* __restrict__ W3, const float* __restrict__ b3,
    float* __restrict__ out)
{
    extern __shared__ float sm[];
    float* sW1t = sm + S_W1T;
    float* sb1  = sm + S_B1;
    float* sW2  = sm + S_W2;
    float* sb2  = sm + S_B2;
    float* sW3  = sm + S_W3;
    float* sb3  = sm + S_B3;

    const int tid = threadIdx.x;

    // stage weights
    for (int i = tid; i < NTOPIN * NT1; i += 128) {
        int k = i >> 7;        // row of W1 (input dim)
        int j = i & 127;       // col (output neuron)
        sW1t[j * 80 + k] = W1[i];
    }
    if (tid < 128) {
        sW1t[tid * 80 + 79] = 0.f;   // pad so float4 over k=76..79 is safe
        sb1[tid] = b1[tid];
    }
    for (int i = tid; i < NT1 * NT2; i += 128) sW2[i] = W2[i];
    if (tid < 64) { sb2[tid] = b2[tid]; sW3[tid] = W3[tid]; }
    if (tid == 0) sb3[0] = b3[0];
    __syncthreads();

    const int s = blockIdx.x * 128 + tid;

    // load x (coalesced: consecutive lanes -> consecutive samples)
    float x[80];
    #pragma unroll
    for (int k = 0; k < NTOPIN; k++) x[k] = g_xT[k * BB + s];
    x[79] = 0.f;

    float h2[NT2];
    #pragma unroll
    for (int m = 0; m < NT2; m++) h2[m] = sb2[m];

    #pragma unroll 2
    for (int j = 0; j < NT1; j++) {
        const float4* w4 = (const float4*)(sW1t + j * 80);
        float a0 = sb1[j], a1 = 0.f, a2 = 0.f, a3 = 0.f;
        #pragma unroll
        for (int q = 0; q < 20; q++) {
            float4 w = w4[q];
            a0 = fmaf(x[4 * q + 0], w.x, a0);
            a1 = fmaf(x[4 * q + 1], w.y, a1);
            a2 = fmaf(x[4 * q + 2], w.z, a2);
            a3 = fmaf(x[4 * q + 3], w.w, a3);
        }
        float h = fmaxf((a0 + a1) + (a2 + a3), 0.f);

        const float4* v4 = (const float4*)(sW2 + j * 64);
        #pragma unroll
        for (int q = 0; q < 16; q++) {
            float4 w = v4[q];
            h2[4 * q + 0] = fmaf(h, w.x, h2[4 * q + 0]);
            h2[4 * q + 1] = fmaf(h, w.y, h2[4 * q + 1]);
            h2[4 * q + 2] = fmaf(h, w.z, h2[4 * q + 2]);
            h2[4 * q + 3] = fmaf(h, w.w, h2[4 * q + 3]);
        }
    }

    float z = sb3[0];
    #pragma unroll
    for (int m = 0; m < NT2; m++)
        z = fmaf(fmaxf(h2[m], 0.f), sW3[m], z);

    out[s] = 1.f / (1.f + __expf(-z));
}

// ---------------------------------------------------------------------------
extern "C" void kernel_launch(void* const* d_in, const int* in_sizes, int n_in,
                              void* d_out, int out_size)
{
    const int*   user       = (const int*)  d_in[0];
    const int*   item       = (const int*)  d_in[1];
    const int*   brand_idx  = (const int*)  d_in[2];
    const int*   cat_idx    = (const int*)  d_in[3];
    const int*   cat_len    = (const int*)  d_in[4];
    const int*   text_idx   = (const int*)  d_in[5];
    const int*   text_len   = (const int*)  d_in[6];
    const float* sales_rank = (const float*)d_in[7];
    const float* user_tab   = (const float*)d_in[8];
    const float* item_tab   = (const float*)d_in[9];
    const float* brand_tab  = (const float*)d_in[10];
    const float* cat_tab    = (const float*)d_in[11];
    const float* text_tab   = (const float*)d_in[12];
    const float* W_bot      = (const float*)d_in[13];
    const float* b_bot      = (const float*)d_in[14];
    const float* W_proj     = (const float*)d_in[15];
    const float* b_proj     = (const float*)d_in[16];
    const float* W_t1       = (const float*)d_in[17];
    const float* b_t1       = (const float*)d_in[18];
    const float* W_t2       = (const float*)d_in[19];
    const float* b_t2       = (const float*)d_in[20];
    const float* W_t3       = (const float*)d_in[21];
    const float* b_t3       = (const float*)d_in[22];
    float* out = (float*)d_out;

    static int smem_set = 0;
    const int smem_bytes = S_TOT * (int)sizeof(float);
    if (!smem_set) {
        cudaFuncSetAttribute(top_kernel,
                             cudaFuncAttributeMaxDynamicSharedMemorySize,
                             smem_bytes);
        smem_set = 1;
    }

    // Kernel 1: warp per sample -> 16384 warps = 2048 blocks x 256 threads
    feat_kernel<<<BB / 8, 256>>>(
        user, item, brand_idx, cat_idx, cat_len, text_idx, text_len,
        sales_rank, user_tab, item_tab, brand_tab, cat_tab, text_tab,
        W_bot, b_bot, W_proj, b_proj);

    // Kernel 2: lane per sample -> 128 blocks x 128 threads
    top_kernel<<<BB / 128, 128, smem_bytes>>>(
        W_t1, b_t1, W_t2, b_t2, W_t3, b_t3, out);
}

// round 2
// speedup vs baseline: 1.3625x; 1.3625x over previous
#include <cuda_runtime.h>

#define BB 16384
#define DD 64
#define LCAT 8
#define LTXT 64
#define NTOPIN 79
#define NT1 128
#define NT2 64

// Transposed intermediate: xT[k][s], k in [0,79), s in [0,B)
__device__ float g_xT[NTOPIN * BB];

// ---------------------------------------------------------------------------
// packed-fp32x2 helpers (FFMA2 — only reachable via PTX fma.rn.f32x2)
// ---------------------------------------------------------------------------
typedef unsigned long long u64;

__device__ __forceinline__ void ffma2(u64& d, u64 a, u64 b) {
    asm("fma.rn.f32x2 %0, %1, %2, %0;" : "+l"(d) : "l"(a), "l"(b));
}
__device__ __forceinline__ u64 pack2(float lo, float hi) {
    u64 u;
    asm("mov.b64 %0, {%1, %2};" : "=l"(u) : "f"(lo), "f"(hi));
    return u;
}
__device__ __forceinline__ float2 unpack2(u64 u) {
    float2 v;
    asm("mov.b64 {%0, %1}, %2;" : "=f"(v.x), "=f"(v.y) : "l"(u));
    return v;
}

// ---------------------------------------------------------------------------
// Kernel 1: warp-per-sample. Gathers, mean-bags, bottom MLP, projection,
// pairwise interactions. Writes xT (transposed) for kernel 2.
// Bags use float4 loads: 2 rows per warp-load (lanes 0-15 row i, 16-31 row i+1).
// ---------------------------------------------------------------------------
__global__ __launch_bounds__(256) void feat_kernel(
    const int* __restrict__ user, const int* __restrict__ item,
    const int* __restrict__ brand, const int* __restrict__ cat_idx,
    const int* __restrict__ cat_len, const int* __restrict__ text_idx,
    const int* __restrict__ text_len, const float* __restrict__ sales_rank,
    const float* __restrict__ user_tab, const float* __restrict__ item_tab,
    const float* __restrict__ brand_tab, const float* __restrict__ cat_tab,
    const float* __restrict__ text_tab,
    const float* __restrict__ W_bot, const float* __restrict__ b_bot,
    const float* __restrict__ W_proj, const float* __restrict__ b_proj)
{
    const unsigned FULL = 0xFFFFFFFFu;
    int gwarp = (blockIdx.x * blockDim.x + threadIdx.x) >> 5;
    int lane  = threadIdx.x & 31;
    if (gwarp >= BB) return;
    const int s = gwarp;

    const float2* ut = (const float2*)user_tab;
    const float2* it = (const float2*)item_tab;
    const float2* bt = (const float2*)brand_tab;
    const float4* ct4 = (const float4*)cat_tab;
    const float4* tt4 = (const float4*)text_tab;

    const int sub = lane >> 4;     // 0: even row, 1: odd row
    const int q   = lane & 15;     // float4 slot within a row

    // ---- single-row gathers (float2 per lane, full warp per row) ----
    int ui = user[s];
    int ii = item[s];
    int bi = brand[s];
    float2 fu = ut[(size_t)ui * 32 + lane];
    float2 fi = it[(size_t)ii * 32 + lane];
    float2 fb = bt[(size_t)bi * 32 + lane];

    // ---- cat mean bag (len in [0,8]), 2 rows per iteration ----
    int clen = cat_len[s];
    int creg = (lane < LCAT) ? cat_idx[s * LCAT + lane] : 0;
    float4 cacc = make_float4(0.f, 0.f, 0.f, 0.f);
    int i = 0;
    #pragma unroll 2
    for (; i + 1 < clen; i += 2) {
        int r = i + sub;
        int idx = __shfl_sync(FULL, creg, r);
        float4 v = ct4[(size_t)idx * 16 + q];
        cacc.x += v.x; cacc.y += v.y; cacc.z += v.z; cacc.w += v.w;
    }
    if (i < clen) {
        int idx = __shfl_sync(FULL, creg, i);
        if (lane < 16) {
            float4 v = ct4[(size_t)idx * 16 + q];
            cacc.x += v.x; cacc.y += v.y; cacc.z += v.z; cacc.w += v.w;
        }
    }

    // ---- text mean bag (len in [1,64]), 2 rows per iteration ----
    int tlen = text_len[s];
    int t0 = text_idx[s * LTXT + lane];
    int t1 = text_idx[s * LTXT + 32 + lane];
    float4 tacc = make_float4(0.f, 0.f, 0.f, 0.f);
    i = 0;
    #pragma unroll 4
    for (; i + 1 < tlen; i += 2) {
        int r = i + sub;
        int idx = __shfl_sync(FULL, (r < 32) ? t0 : t1, r & 31);
        float4 v = tt4[(size_t)idx * 16 + q];
        tacc.x += v.x; tacc.y += v.y; tacc.z += v.z; tacc.w += v.w;
    }
    if (i < tlen) {
        int idx = __shfl_sync(FULL, (i < 32) ? t0 : t1, i & 31);
        if (lane < 16) {
            float4 v = tt4[(size_t)idx * 16 + q];
            tacc.x += v.x; tacc.y += v.y; tacc.z += v.z; tacc.w += v.w;
        }
    }

    // combine parity halves (result valid in lanes 0-15) and scale
    {
        float cinv = 1.f / (float)max(clen, 1);
        float tinv = 1.f / (float)max(tlen, 1);
        cacc.x = (cacc.x + __shfl_down_sync(FULL, cacc.x, 16)) * cinv;
        cacc.y = (cacc.y + __shfl_down_sync(FULL, cacc.y, 16)) * cinv;
        cacc.z = (cacc.z + __shfl_down_sync(FULL, cacc.z, 16)) * cinv;
        cacc.w = (cacc.w + __shfl_down_sync(FULL, cacc.w, 16)) * cinv;
        tacc.x = (tacc.x + __shfl_down_sync(FULL, tacc.x, 16)) * tinv;
        tacc.y = (tacc.y + __shfl_down_sync(FULL, tacc.y, 16)) * tinv;
        tacc.z = (tacc.z + __shfl_down_sync(FULL, tacc.z, 16)) * tinv;
        tacc.w = (tacc.w + __shfl_down_sync(FULL, tacc.w, 16)) * tinv;
    }

    // convert float4-in-lanes-0..15 -> float2-per-lane (lane L owns dims 2L,2L+1)
    float2 cv, tv;
    {
        int src = lane >> 1;
        float cx = __shfl_sync(FULL, cacc.x, src);
        float cy = __shfl_sync(FULL, cacc.y, src);
        float cz = __shfl_sync(FULL, cacc.z, src);
        float cw = __shfl_sync(FULL, cacc.w, src);
        float tx = __shfl_sync(FULL, tacc.x, src);
        float ty = __shfl_sync(FULL, tacc.y, src);
        float tz = __shfl_sync(FULL, tacc.z, src);
        float tw = __shfl_sync(FULL, tacc.w, src);
        if (lane & 1) { cv = make_float2(cz, cw); tv = make_float2(tz, tw); }
        else          { cv = make_float2(cx, cy); tv = make_float2(tx, ty); }
    }

    // ---- bottom MLP: dense = relu(sr * W_bot + b_bot), 64 wide ----
    float sr = sales_rank[s];
    float d0 = fmaxf(fmaf(sr, W_bot[2 * lane],     b_bot[2 * lane]),     0.f);
    float d1 = fmaxf(fmaf(sr, W_bot[2 * lane + 1], b_bot[2 * lane + 1]), 0.f);

    // ---- projection: dense_use = dense @ W_proj + b_proj ----
    const float2* wp = (const float2*)W_proj;
    float2 du = make_float2(b_proj[2 * lane], b_proj[2 * lane + 1]);
    #pragma unroll
    for (int k = 0; k < DD; k++) {
        float dk = __shfl_sync(FULL, (k & 1) ? d1 : d0, k >> 1);
        float2 w = wp[k * 32 + lane];
        du.x = fmaf(dk, w.x, du.x);
        du.y = fmaf(dk, w.y, du.y);
    }

    // ---- pairwise interactions (15 upper-tri pairs of 6 features) ----
    float2 f[6];
    f[0] = fu; f[1] = fi; f[2] = fb; f[3] = cv; f[4] = tv; f[5] = du;

    float keep = 0.f;
    int p = 0;
    #pragma unroll
    for (int a = 0; a < 6; a++) {
        #pragma unroll
        for (int b = a + 1; b < 6; b++) {
            float dv = f[a].x * f[b].x + f[a].y * f[b].y;
            #pragma unroll
            for (int off = 16; off > 0; off >>= 1)
                dv += __shfl_xor_sync(FULL, dv, off);
            if (lane == p) keep = dv;
            p++;
        }
    }

    // ---- write transposed x: [inter(15); dense(64)] ----
    if (lane < 15) g_xT[lane * BB + s] = keep;
    g_xT[(15 + 2 * lane) * BB + s] = d0;
    g_xT[(16 + 2 * lane) * BB + s] = d1;
}

// ---------------------------------------------------------------------------
// Kernel 2: top MLP, FFMA2 (fp32x2) with the reduction dim packed even/odd.
// 128 blocks x 512 threads; block handles 128 samples.
// Stage A: h1 = relu(x @ W1 + b1) cooperatively (4 j-groups of 32 neurons).
// Stage B: h2 = relu(h1 @ W2 + b2); logits; sigmoid.
// All weight LDS are warp-uniform broadcasts; x/h1 LDS are coalesced.
// ---------------------------------------------------------------------------
// dynamic smem layout (bytes):
#define KP1 40                       // ceil(79/2) k-pairs for layer 1
#define OFF_W1P 0                    // u64[KP1][128]
#define OFF_XP  (OFF_W1P + KP1*128*8)        // u64[KP1][128]
#define OFF_W2P (OFF_XP  + KP1*128*8)        // u64[64][64]
#define OFF_H1P (OFF_W2P + 64*64*8)          // u64[64][128]
#define OFF_B1  (OFF_H1P + 64*128*8)         // float[128]
#define OFF_B2  (OFF_B1 + 128*4)             // float[64]
#define OFF_W3  (OFF_B2 + 64*4)              // float[64]
#define OFF_B3  (OFF_W3 + 64*4)              // float[4]
#define OFF_PZ  (OFF_B3 + 16)                // float[4][128]
#define SMEM_BYTES (OFF_PZ + 4*128*4)

__global__ __launch_bounds__(512) void top_kernel(
    const float* __restrict__ W1, const float* __restrict__ b1,
    const float* __restrict__ W2, const float* __restrict__ b2,
    const float* __restrict__ W3, const float* __restrict__ b3,
    float* __restrict__ out)
{
    extern __shared__ __align__(16) char sm[];
    u64*   sW1p = (u64*)(sm + OFF_W1P);
    u64*   sXp  = (u64*)(sm + OFF_XP);
    u64*   sW2p = (u64*)(sm + OFF_W2P);
    u64*   sH1p = (u64*)(sm + OFF_H1P);
    float* sb1  = (float*)(sm + OFF_B1);
    float* sb2  = (float*)(sm + OFF_B2);
    float* sW3  = (float*)(sm + OFF_W3);
    float* sb3  = (float*)(sm + OFF_B3);
    float* sPz  = (float*)(sm + OFF_PZ);

    const int tid = threadIdx.x;
    const int sl  = tid & 127;     // sample slot
    const int jg  = tid >> 7;      // group 0..3
    const int S0  = blockIdx.x * 128;

    // ---- stage weights (k-paired even/odd) and x ----
    // W1p[t][j] = {W1[2t][j], W1[2t+1][j] or 0}
    for (int idx = tid; idx < KP1 * 128; idx += 512) {
        int t = idx >> 7, j = idx & 127;
        float lo = W1[(2 * t) * 128 + j];
        float hi = (2 * t + 1 < NTOPIN) ? W1[(2 * t + 1) * 128 + j] : 0.f;
        sW1p[idx] = pack2(lo, hi);
    }
    // Xp[t][ss] = {xT[2t][S0+ss], xT[2t+1][S0+ss] or 0}
    for (int idx = tid; idx < KP1 * 128; idx += 512) {
        int t = idx >> 7, ss = idx & 127;
        float lo = g_xT[(2 * t) * BB + S0 + ss];
        float hi = (2 * t + 1 < NTOPIN) ? g_xT[(2 * t + 1) * BB + S0 + ss] : 0.f;
        sXp[idx] = pack2(lo, hi);
    }
    // W2p[t][m] = {W2[2t][m], W2[2t+1][m]}
    for (int idx = tid; idx < 64 * 64; idx += 512) {
        int t = idx >> 6, m = idx & 63;
        sW2p[idx] = pack2(W2[(2 * t) * 64 + m], W2[(2 * t + 1) * 64 + m]);
    }
    if (tid < 128) sb1[tid] = b1[tid];
    if (tid < 64) { sb2[tid] = b2[tid]; sW3[tid] = W3[tid]; }
    if (tid == 0) sb3[0] = b3[0];
    __syncthreads();

    // ---- stage A: 32 neurons per thread, in tiles of 8 ----
    #pragma unroll
    for (int jt = 0; jt < 4; jt++) {
        const int jbase = jg * 32 + jt * 8;
        u64 acc[8];
        #pragma unroll
        for (int r = 0; r < 8; r++) acc[r] = pack2(sb1[jbase + r], 0.f);

        #pragma unroll 5
        for (int t = 0; t < KP1; t++) {
            u64 x2 = sXp[t * 128 + sl];
            const ulonglong2* wrow = (const ulonglong2*)(sW1p + t * 128 + jbase);
            #pragma unroll
            for (int r = 0; r < 4; r++) {
                ulonglong2 w = wrow[r];
                ffma2(acc[2 * r],     x2, w.x);
                ffma2(acc[2 * r + 1], x2, w.y);
            }
        }
        // relu(lo+hi), store as pairs into H1p[jp][sl]
        #pragma unroll
        for (int r = 0; r < 8; r += 2) {
            float2 a0 = unpack2(acc[r]);
            float2 a1 = unpack2(acc[r + 1]);
            float h0 = fmaxf(a0.x + a0.y, 0.f);
            float h1 = fmaxf(a1.x + a1.y, 0.f);
            sH1p[((jbase + r) >> 1) * 128 + sl] = pack2(h0, h1);
        }
    }
    __syncthreads();

    // ---- stage B: 16 h2-outputs per thread ----
    const int mbase = jg * 16;
    u64 acc[16];
    #pragma unroll
    for (int r = 0; r < 16; r++) acc[r] = pack2(sb2[mbase + r], 0.f);

    #pragma unroll 4
    for (int t = 0; t < 64; t++) {
        u64 h2v = sH1p[t * 128 + sl];
        const ulonglong2* wrow = (const ulonglong2*)(sW2p + t * 64 + mbase);
        #pragma unroll
        for (int r = 0; r < 8; r++) {
            ulonglong2 w = wrow[r];
            ffma2(acc[2 * r],     h2v, w.x);
            ffma2(acc[2 * r + 1], h2v, w.y);
        }
    }

    // ---- layer 3 partial + cross-group reduction + sigmoid ----
    float z = 0.f;
    #pragma unroll
    for (int r = 0; r < 16; r++) {
        float2 a = unpack2(acc[r]);
        float h2 = fmaxf(a.x + a.y, 0.f);
        z = fmaf(h2, sW3[mbase + r], z);
    }
    sPz[jg * 128 + sl] = z;
    __syncthreads();
    if (jg == 0) {
        float zz = sb3[0] + sPz[sl] + sPz[128 + sl] + sPz[256 + sl] + sPz[384 + sl];
        out[S0 + sl] = 1.f / (1.f + __expf(-zz));
    }
}

// ---------------------------------------------------------------------------
extern "C" void kernel_launch(void* const* d_in, const int* in_sizes, int n_in,
                              void* d_out, int out_size)
{
    const int*   user       = (const int*)  d_in[0];
    const int*   item       = (const int*)  d_in[1];
    const int*   brand_idx  = (const int*)  d_in[2];
    const int*   cat_idx    = (const int*)  d_in[3];
    const int*   cat_len    = (const int*)  d_in[4];
    const int*   text_idx   = (const int*)  d_in[5];
    const int*   text_len   = (const int*)  d_in[6];
    const float* sales_rank = (const float*)d_in[7];
    const float* user_tab   = (const float*)d_in[8];
    const float* item_tab   = (const float*)d_in[9];
    const float* brand_tab  = (const float*)d_in[10];
    const float* cat_tab    = (const float*)d_in[11];
    const float* text_tab   = (const float*)d_in[12];
    const float* W_bot      = (const float*)d_in[13];
    const float* b_bot      = (const float*)d_in[14];
    const float* W_proj     = (const float*)d_in[15];
    const float* b_proj     = (const float*)d_in[16];
    const float* W_t1       = (const float*)d_in[17];
    const float* b_t1       = (const float*)d_in[18];
    const float* W_t2       = (const float*)d_in[19];
    const float* b_t2       = (const float*)d_in[20];
    const float* W_t3       = (const float*)d_in[21];
    const float* b_t3       = (const float*)d_in[22];
    float* out = (float*)d_out;

    cudaFuncSetAttribute(top_kernel,
                         cudaFuncAttributeMaxDynamicSharedMemorySize,
                         SMEM_BYTES);

    // Kernel 1: warp per sample -> 16384 warps = 2048 blocks x 256 threads
    feat_kernel<<<BB / 8, 256>>>(
        user, item, brand_idx, cat_idx, cat_len, text_idx, text_len,
        sales_rank, user_tab, item_tab, brand_tab, cat_tab, text_tab,
        W_bot, b_bot, W_proj, b_proj);

    // Kernel 2: 128 blocks x 512 threads, 128 samples per block
    top_kernel<<<128, 512, SMEM_BYTES>>>(
        W_t1, b_t1, W_t2, b_t2, W_t3, b_t3, out);
}

// round 3
// speedup vs baseline: 1.7103x; 1.2553x over previous
#include <cuda_runtime.h>

#define BB 16384
#define DD 64
#define LCAT 8
#define LTXT 64
#define NTOPIN 79
#define NT1 128
#define NT2 64

// Transposed intermediate: xT[k][s], k in [0,79), s in [0,B)
__device__ float g_xT[NTOPIN * BB];

// ---------------------------------------------------------------------------
// packed-fp32x2 helpers (FFMA2 — only reachable via PTX fma.rn.f32x2)
// ---------------------------------------------------------------------------
typedef unsigned long long u64;

__device__ __forceinline__ void ffma2(u64& d, u64 a, u64 b) {
    asm("fma.rn.f32x2 %0, %1, %2, %0;" : "+l"(d) : "l"(a), "l"(b));
}
__device__ __forceinline__ u64 pack2(float lo, float hi) {
    u64 u;
    asm("mov.b64 %0, {%1, %2};" : "=l"(u) : "f"(lo), "f"(hi));
    return u;
}
__device__ __forceinline__ float2 unpack2(u64 u) {
    float2 v;
    asm("mov.b64 {%0, %1}, %2;" : "=f"(v.x), "=f"(v.y) : "l"(u));
    return v;
}

// ---------------------------------------------------------------------------
// Kernel 1: warp-per-sample. Gathers, mean-bags, bottom MLP, projection,
// pairwise interactions. Writes xT (transposed) for kernel 2.
// Bags use float4 loads: 2 rows per warp-load (lanes 0-15 row i, 16-31 row i+1).
// Streaming loads (__ldcs) keep the >1GB tables from thrashing L2.
// ---------------------------------------------------------------------------
__global__ __launch_bounds__(256) void feat_kernel(
    const int* __restrict__ user, const int* __restrict__ item,
    const int* __restrict__ brand, const int* __restrict__ cat_idx,
    const int* __restrict__ cat_len, const int* __restrict__ text_idx,
    const int* __restrict__ text_len, const float* __restrict__ sales_rank,
    const float* __restrict__ user_tab, const float* __restrict__ item_tab,
    const float* __restrict__ brand_tab, const float* __restrict__ cat_tab,
    const float* __restrict__ text_tab,
    const float* __restrict__ W_bot, const float* __restrict__ b_bot,
    const float* __restrict__ W_proj, const float* __restrict__ b_proj)
{
    const unsigned FULL = 0xFFFFFFFFu;
    int gwarp = (blockIdx.x * blockDim.x + threadIdx.x) >> 5;
    int lane  = threadIdx.x & 31;
    if (gwarp >= BB) return;
    const int s = gwarp;

    const float2* ut = (const float2*)user_tab;
    const float2* it = (const float2*)item_tab;
    const float2* bt = (const float2*)brand_tab;
    const float4* ct4 = (const float4*)cat_tab;
    const float4* tt4 = (const float4*)text_tab;

    const int sub = lane >> 4;     // 0: even row, 1: odd row
    const int q   = lane & 15;     // float4 slot within a row

    // ---- single-row gathers (float2 per lane, full warp per row) ----
    int ui = user[s];
    int ii = item[s];
    int bi = brand[s];
    float2 fu = __ldcs(ut + (size_t)ui * 32 + lane);
    float2 fi = __ldcs(it + (size_t)ii * 32 + lane);
    float2 fb = __ldcs(bt + (size_t)bi * 32 + lane);

    // ---- cat mean bag (len in [0,8]), 2 rows per iteration ----
    int clen = cat_len[s];
    int creg = (lane < LCAT) ? cat_idx[s * LCAT + lane] : 0;
    float4 cacc = make_float4(0.f, 0.f, 0.f, 0.f);
    int i = 0;
    #pragma unroll 4
    for (; i + 1 < clen; i += 2) {
        int r = i + sub;
        int idx = __shfl_sync(FULL, creg, r);
        float4 v = __ldcs(ct4 + (size_t)idx * 16 + q);
        cacc.x += v.x; cacc.y += v.y; cacc.z += v.z; cacc.w += v.w;
    }
    if (i < clen) {
        int idx = __shfl_sync(FULL, creg, i);
        if (lane < 16) {
            float4 v = __ldcs(ct4 + (size_t)idx * 16 + q);
            cacc.x += v.x; cacc.y += v.y; cacc.z += v.z; cacc.w += v.w;
        }
    }

    // ---- text mean bag (len in [1,64]), 2 rows per iteration ----
    int tlen = text_len[s];
    int t0 = text_idx[s * LTXT + lane];
    int t1 = text_idx[s * LTXT + 32 + lane];
    float4 tacc = make_float4(0.f, 0.f, 0.f, 0.f);
    i = 0;
    #pragma unroll 8
    for (; i + 1 < tlen; i += 2) {
        int r = i + sub;
        int idx = __shfl_sync(FULL, (r < 32) ? t0 : t1, r & 31);
        float4 v = __ldcs(tt4 + (size_t)idx * 16 + q);
        tacc.x += v.x; tacc.y += v.y; tacc.z += v.z; tacc.w += v.w;
    }
    if (i < tlen) {
        int idx = __shfl_sync(FULL, (i < 32) ? t0 : t1, i & 31);
        if (lane < 16) {
            float4 v = __ldcs(tt4 + (size_t)idx * 16 + q);
            tacc.x += v.x; tacc.y += v.y; tacc.z += v.z; tacc.w += v.w;
        }
    }

    // combine parity halves (result valid in lanes 0-15) and scale
    {
        float cinv = 1.f / (float)max(clen, 1);
        float tinv = 1.f / (float)max(tlen, 1);
        cacc.x = (cacc.x + __shfl_down_sync(FULL, cacc.x, 16)) * cinv;
        cacc.y = (cacc.y + __shfl_down_sync(FULL, cacc.y, 16)) * cinv;
        cacc.z = (cacc.z + __shfl_down_sync(FULL, cacc.z, 16)) * cinv;
        cacc.w = (cacc.w + __shfl_down_sync(FULL, cacc.w, 16)) * cinv;
        tacc.x = (tacc.x + __shfl_down_sync(FULL, tacc.x, 16)) * tinv;
        tacc.y = (tacc.y + __shfl_down_sync(FULL, tacc.y, 16)) * tinv;
        tacc.z = (tacc.z + __shfl_down_sync(FULL, tacc.z, 16)) * tinv;
        tacc.w = (tacc.w + __shfl_down_sync(FULL, tacc.w, 16)) * tinv;
    }

    // convert float4-in-lanes-0..15 -> float2-per-lane (lane L owns dims 2L,2L+1)
    float2 cv, tv;
    {
        int src = lane >> 1;
        float cx = __shfl_sync(FULL, cacc.x, src);
        float cy = __shfl_sync(FULL, cacc.y, src);
        float cz = __shfl_sync(FULL, cacc.z, src);
        float cw = __shfl_sync(FULL, cacc.w, src);
        float tx = __shfl_sync(FULL, tacc.x, src);
        float ty = __shfl_sync(FULL, tacc.y, src);
        float tz = __shfl_sync(FULL, tacc.z, src);
        float tw = __shfl_sync(FULL, tacc.w, src);
        if (lane & 1) { cv = make_float2(cz, cw); tv = make_float2(tz, tw); }
        else          { cv = make_float2(cx, cy); tv = make_float2(tx, ty); }
    }

    // ---- bottom MLP: dense = relu(sr * W_bot + b_bot), 64 wide ----
    float sr = sales_rank[s];
    float d0 = fmaxf(fmaf(sr, W_bot[2 * lane],     b_bot[2 * lane]),     0.f);
    float d1 = fmaxf(fmaf(sr, W_bot[2 * lane + 1], b_bot[2 * lane + 1]), 0.f);

    // ---- projection: dense_use = dense @ W_proj + b_proj ----
    const float2* wp = (const float2*)W_proj;
    float2 du = make_float2(b_proj[2 * lane], b_proj[2 * lane + 1]);
    #pragma unroll
    for (int k = 0; k < DD; k++) {
        float dk = __shfl_sync(FULL, (k & 1) ? d1 : d0, k >> 1);
        float2 w = wp[k * 32 + lane];
        du.x = fmaf(dk, w.x, du.x);
        du.y = fmaf(dk, w.y, du.y);
    }

    // ---- pairwise interactions (15 upper-tri pairs of 6 features) ----
    float2 f[6];
    f[0] = fu; f[1] = fi; f[2] = fb; f[3] = cv; f[4] = tv; f[5] = du;

    float keep = 0.f;
    int p = 0;
    #pragma unroll
    for (int a = 0; a < 6; a++) {
        #pragma unroll
        for (int b = a + 1; b < 6; b++) {
            float dv = f[a].x * f[b].x + f[a].y * f[b].y;
            #pragma unroll
            for (int off = 16; off > 0; off >>= 1)
                dv += __shfl_xor_sync(FULL, dv, off);
            if (lane == p) keep = dv;
            p++;
        }
    }

    // ---- write transposed x: [inter(15); dense(64)] ----
    if (lane < 15) g_xT[lane * BB + s] = keep;
    g_xT[(15 + 2 * lane) * BB + s] = d0;
    g_xT[(16 + 2 * lane) * BB + s] = d1;
}

// ---------------------------------------------------------------------------
// Kernel 2: top MLP, FFMA2, 128 blocks x 1024 threads (8 j-groups x 128
// samples). 32 warps/SM for latency hiding.
// Stage A: h1 = relu(x @ W1 + b1), 16 neurons/thread in 2 tiles of 8.
// Stage B: h2 = relu(h1 @ W2 + b2), 8 outputs/thread; layer3 + sigmoid.
// ---------------------------------------------------------------------------
#define KP1 40                       // ceil(79/2) k-pairs for layer 1
#define OFF_W1P 0                    // u64[KP1][128]
#define OFF_XP  (OFF_W1P + KP1*128*8)        // u64[KP1][128]
#define OFF_W2P (OFF_XP  + KP1*128*8)        // u64[64][64]
#define OFF_H1P (OFF_W2P + 64*64*8)          // u64[64][128]
#define OFF_B1  (OFF_H1P + 64*128*8)         // float[128]
#define OFF_B2  (OFF_B1 + 128*4)             // float[64]
#define OFF_W3  (OFF_B2 + 64*4)              // float[64]
#define OFF_B3  (OFF_W3 + 64*4)              // float[4]
#define OFF_PZ  (OFF_B3 + 16)                // float[8][128]
#define SMEM_BYTES (OFF_PZ + 8*128*4)

__global__ __launch_bounds__(1024) void top_kernel(
    const float* __restrict__ W1, const float* __restrict__ b1,
    const float* __restrict__ W2, const float* __restrict__ b2,
    const float* __restrict__ W3, const float* __restrict__ b3,
    float* __restrict__ out)
{
    extern __shared__ __align__(16) char sm[];
    u64*   sW1p = (u64*)(sm + OFF_W1P);
    u64*   sXp  = (u64*)(sm + OFF_XP);
    u64*   sW2p = (u64*)(sm + OFF_W2P);
    u64*   sH1p = (u64*)(sm + OFF_H1P);
    float* sb1  = (float*)(sm + OFF_B1);
    float* sb2  = (float*)(sm + OFF_B2);
    float* sW3  = (float*)(sm + OFF_W3);
    float* sb3  = (float*)(sm + OFF_B3);
    float* sPz  = (float*)(sm + OFF_PZ);

    const int tid = threadIdx.x;
    const int sl  = tid & 127;     // sample slot
    const int jg  = tid >> 7;      // group 0..7
    const int S0  = blockIdx.x * 128;

    // ---- stage weights (k-paired even/odd) and x ----
    for (int idx = tid; idx < KP1 * 128; idx += 1024) {
        int t = idx >> 7, j = idx & 127;
        float lo = W1[(2 * t) * 128 + j];
        float hi = (2 * t + 1 < NTOPIN) ? W1[(2 * t + 1) * 128 + j] : 0.f;
        sW1p[idx] = pack2(lo, hi);
    }
    for (int idx = tid; idx < KP1 * 128; idx += 1024) {
        int t = idx >> 7, ss = idx & 127;
        float lo = g_xT[(2 * t) * BB + S0 + ss];
        float hi = (2 * t + 1 < NTOPIN) ? g_xT[(2 * t + 1) * BB + S0 + ss] : 0.f;
        sXp[idx] = pack2(lo, hi);
    }
    for (int idx = tid; idx < 64 * 64; idx += 1024) {
        int t = idx >> 6, m = idx & 63;
        sW2p[idx] = pack2(W2[(2 * t) * 64 + m], W2[(2 * t + 1) * 64 + m]);
    }
    if (tid < 128) sb1[tid] = b1[tid];
    if (tid < 64) { sb2[tid] = b2[tid]; sW3[tid] = W3[tid]; }
    if (tid == 0) sb3[0] = b3[0];
    __syncthreads();

    // ---- stage A: 16 neurons per thread, in 2 tiles of 8 ----
    #pragma unroll
    for (int jt = 0; jt < 2; jt++) {
        const int jbase = jg * 16 + jt * 8;
        u64 acc[8];
        #pragma unroll
        for (int r = 0; r < 8; r++) acc[r] = pack2(sb1[jbase + r], 0.f);

        #pragma unroll 4
        for (int t = 0; t < KP1; t++) {
            u64 x2 = sXp[t * 128 + sl];
            const ulonglong2* wrow = (const ulonglong2*)(sW1p + t * 128 + jbase);
            #pragma unroll
            for (int r = 0; r < 4; r++) {
                ulonglong2 w = wrow[r];
                ffma2(acc[2 * r],     x2, w.x);
                ffma2(acc[2 * r + 1], x2, w.y);
            }
        }
        // relu(lo+hi), store as pairs into H1p[jp][sl]
        #pragma unroll
        for (int r = 0; r < 8; r += 2) {
            float2 a0 = unpack2(acc[r]);
            float2 a1 = unpack2(acc[r + 1]);
            float h0 = fmaxf(a0.x + a0.y, 0.f);
            float h1 = fmaxf(a1.x + a1.y, 0.f);
            sH1p[((jbase + r) >> 1) * 128 + sl] = pack2(h0, h1);
        }
    }
    __syncthreads();

    // ---- stage B: 8 h2-outputs per thread ----
    const int mbase = jg * 8;
    u64 acc[8];
    #pragma unroll
    for (int r = 0; r < 8; r++) acc[r] = pack2(sb2[mbase + r], 0.f);

    #pragma unroll 4
    for (int t = 0; t < 64; t++) {
        u64 h2v = sH1p[t * 128 + sl];
        const ulonglong2* wrow = (const ulonglong2*)(sW2p + t * 64 + mbase);
        #pragma unroll
        for (int r = 0; r < 4; r++) {
            ulonglong2 w = wrow[r];
            ffma2(acc[2 * r],     h2v, w.x);
            ffma2(acc[2 * r + 1], h2v, w.y);
        }
    }

    // ---- layer 3 partial + cross-group reduction + sigmoid ----
    float z = 0.f;
    #pragma unroll
    for (int r = 0; r < 8; r++) {
        float2 a = unpack2(acc[r]);
        float h2 = fmaxf(a.x + a.y, 0.f);
        z = fmaf(h2, sW3[mbase + r], z);
    }
    sPz[jg * 128 + sl] = z;
    __syncthreads();
    if (jg == 0) {
        float zz = sb3[0];
        #pragma unroll
        for (int g = 0; g < 8; g++) zz += sPz[g * 128 + sl];
        out[S0 + sl] = 1.f / (1.f + __expf(-zz));
    }
}

// ---------------------------------------------------------------------------
extern "C" void kernel_launch(void* const* d_in, const int* in_sizes, int n_in,
                              void* d_out, int out_size)
{
    const int*   user       = (const int*)  d_in[0];
    const int*   item       = (const int*)  d_in[1];
    const int*   brand_idx  = (const int*)  d_in[2];
    const int*   cat_idx    = (const int*)  d_in[3];
    const int*   cat_len    = (const int*)  d_in[4];
    const int*   text_idx   = (const int*)  d_in[5];
    const int*   text_len   = (const int*)  d_in[6];
    const float* sales_rank = (const float*)d_in[7];
    const float* user_tab   = (const float*)d_in[8];
    const float* item_tab   = (const float*)d_in[9];
    const float* brand_tab  = (const float*)d_in[10];
    const float* cat_tab    = (const float*)d_in[11];
    const float* text_tab   = (const float*)d_in[12];
    const float* W_bot      = (const float*)d_in[13];
    const float* b_bot      = (const float*)d_in[14];
    const float* W_proj     = (const float*)d_in[15];
    const float* b_proj     = (const float*)d_in[16];
    const float* W_t1       = (const float*)d_in[17];
    const float* b_t1       = (const float*)d_in[18];
    const float* W_t2       = (const float*)d_in[19];
    const float* b_t2       = (const float*)d_in[20];
    const float* W_t3       = (const float*)d_in[21];
    const float* b_t3       = (const float*)d_in[22];
    float* out = (float*)d_out;

    cudaFuncSetAttribute(top_kernel,
                         cudaFuncAttributeMaxDynamicSharedMemorySize,
                         SMEM_BYTES);

    // Kernel 1: warp per sample -> 16384 warps = 2048 blocks x 256 threads
    feat_kernel<<<BB / 8, 256>>>(
        user, item, brand_idx, cat_idx, cat_len, text_idx, text_len,
        sales_rank, user_tab, item_tab, brand_tab, cat_tab, text_tab,
        W_bot, b_bot, W_proj, b_proj);

    // Kernel 2: 128 blocks x 1024 threads, 128 samples per block
    top_kernel<<<128, 1024, SMEM_BYTES>>>(
        W_t1, b_t1, W_t2, b_t2, W_t3, b_t3, out);
}

// round 4
// speedup vs baseline: 1.7909x; 1.0471x over previous
#include <cuda_runtime.h>

#define BB 16384
#define DD 64
#define LCAT 8
#define LTXT 64
#define NTOPIN 79
#define NT1 128
#define NT2 64

// Transposed intermediate: xT[k][s], k in [0,79), s in [0,B)
__device__ float g_xT[NTOPIN * BB];

// ---------------------------------------------------------------------------
// packed-fp32x2 helpers (FFMA2 — only reachable via PTX fma.rn.f32x2)
// ---------------------------------------------------------------------------
typedef unsigned long long u64;

__device__ __forceinline__ void ffma2(u64& d, u64 a, u64 b) {
    asm("fma.rn.f32x2 %0, %1, %2, %0;" : "+l"(d) : "l"(a), "l"(b));
}
__device__ __forceinline__ u64 pack2(float lo, float hi) {
    u64 u;
    asm("mov.b64 %0, {%1, %2};" : "=l"(u) : "f"(lo), "f"(hi));
    return u;
}
__device__ __forceinline__ float2 unpack2(u64 u) {
    float2 v;
    asm("mov.b64 {%0, %1}, %2;" : "=f"(v.x), "=f"(v.y) : "l"(u));
    return v;
}

// ---------------------------------------------------------------------------
// Kernel 1: warp-per-sample. Gathers, mean-bags, bottom MLP, projection,
// pairwise interactions. Writes xT (transposed) for kernel 2.
// Bag loops are FIXED-TRIP fully-unrolled with predicated loads so that all
// gathers are issued up-front (max MLP); 2 rows per warp-load.
// ---------------------------------------------------------------------------
__global__ __launch_bounds__(256) void feat_kernel(
    const int* __restrict__ user, const int* __restrict__ item,
    const int* __restrict__ brand, const int* __restrict__ cat_idx,
    const int* __restrict__ cat_len, const int* __restrict__ text_idx,
    const int* __restrict__ text_len, const float* __restrict__ sales_rank,
    const float* __restrict__ user_tab, const float* __restrict__ item_tab,
    const float* __restrict__ brand_tab, const float* __restrict__ cat_tab,
    const float* __restrict__ text_tab,
    const float* __restrict__ W_bot, const float* __restrict__ b_bot,
    const float* __restrict__ W_proj, const float* __restrict__ b_proj)
{
    const unsigned FULL = 0xFFFFFFFFu;
    int gwarp = (blockIdx.x * blockDim.x + threadIdx.x) >> 5;
    int lane  = threadIdx.x & 31;
    if (gwarp >= BB) return;
    const int s = gwarp;

    const float2* ut = (const float2*)user_tab;
    const float2* it = (const float2*)item_tab;
    const float2* bt = (const float2*)brand_tab;
    const float4* ct4 = (const float4*)cat_tab;
    const float4* tt4 = (const float4*)text_tab;

    const int sub = lane >> 4;     // 0: even row, 1: odd row
    const int q   = lane & 15;     // float4 slot within a row

    // ---- single-row gathers (float2 per lane, full warp per row) ----
    int ui = user[s];
    int ii = item[s];
    int bi = brand[s];
    float2 fu = __ldcs(ut + (size_t)ui * 32 + lane);
    float2 fi = __ldcs(it + (size_t)ii * 32 + lane);
    float2 fb = bt[(size_t)bi * 32 + lane];   // 25MB table: let L2 cache it

    int clen = cat_len[s];
    int tlen = text_len[s];
    int creg = (lane < LCAT) ? cat_idx[s * LCAT + lane] : 0;
    int t0 = text_idx[s * LTXT + lane];
    int t1 = text_idx[s * LTXT + 32 + lane];

    // ---- cat mean bag (len in [0,8]): fixed 4 pair-iterations, predicated ----
    float4 cacc = make_float4(0.f, 0.f, 0.f, 0.f);
    #pragma unroll
    for (int i = 0; i < LCAT; i += 2) {
        int r = i + sub;
        int idx = __shfl_sync(FULL, creg, r);
        if (r < clen) {                               // 1.28MB table -> L2 hits
            float4 v = ct4[(size_t)idx * 16 + q];
            cacc.x += v.x; cacc.y += v.y; cacc.z += v.z; cacc.w += v.w;
        }
    }

    // ---- text mean bag (len in [1,64]): fixed 32 pair-iterations, predicated ----
    float4 tacc = make_float4(0.f, 0.f, 0.f, 0.f);
    #pragma unroll
    for (int i = 0; i < LTXT; i += 2) {
        int r = i + sub;
        int idx = __shfl_sync(FULL, (i < 32) ? t0 : t1, r & 31);
        if (r < tlen) {
            float4 v = __ldcs(tt4 + (size_t)idx * 16 + q);
            tacc.x += v.x; tacc.y += v.y; tacc.z += v.z; tacc.w += v.w;
        }
    }

    // combine parity halves (result valid in lanes 0-15) and scale
    {
        float cinv = 1.f / (float)max(clen, 1);
        float tinv = 1.f / (float)max(tlen, 1);
        cacc.x = (cacc.x + __shfl_down_sync(FULL, cacc.x, 16)) * cinv;
        cacc.y = (cacc.y + __shfl_down_sync(FULL, cacc.y, 16)) * cinv;
        cacc.z = (cacc.z + __shfl_down_sync(FULL, cacc.z, 16)) * cinv;
        cacc.w = (cacc.w + __shfl_down_sync(FULL, cacc.w, 16)) * cinv;
        tacc.x = (tacc.x + __shfl_down_sync(FULL, tacc.x, 16)) * tinv;
        tacc.y = (tacc.y + __shfl_down_sync(FULL, tacc.y, 16)) * tinv;
        tacc.z = (tacc.z + __shfl_down_sync(FULL, tacc.z, 16)) * tinv;
        tacc.w = (tacc.w + __shfl_down_sync(FULL, tacc.w, 16)) * tinv;
    }

    // convert float4-in-lanes-0..15 -> float2-per-lane (lane L owns dims 2L,2L+1)
    float2 cv, tv;
    {
        int src = lane >> 1;
        float cx = __shfl_sync(FULL, cacc.x, src);
        float cy = __shfl_sync(FULL, cacc.y, src);
        float cz = __shfl_sync(FULL, cacc.z, src);
        float cw = __shfl_sync(FULL, cacc.w, src);
        float tx = __shfl_sync(FULL, tacc.x, src);
        float ty = __shfl_sync(FULL, tacc.y, src);
        float tz = __shfl_sync(FULL, tacc.z, src);
        float tw = __shfl_sync(FULL, tacc.w, src);
        if (lane & 1) { cv = make_float2(cz, cw); tv = make_float2(tz, tw); }
        else          { cv = make_float2(cx, cy); tv = make_float2(tx, ty); }
    }

    // ---- bottom MLP: dense = relu(sr * W_bot + b_bot), 64 wide ----
    float sr = sales_rank[s];
    float d0 = fmaxf(fmaf(sr, W_bot[2 * lane],     b_bot[2 * lane]),     0.f);
    float d1 = fmaxf(fmaf(sr, W_bot[2 * lane + 1], b_bot[2 * lane + 1]), 0.f);

    // ---- projection: dense_use = dense @ W_proj + b_proj ----
    const float2* wp = (const float2*)W_proj;
    float2 du = make_float2(b_proj[2 * lane], b_proj[2 * lane + 1]);
    #pragma unroll
    for (int k = 0; k < DD; k++) {
        float dk = __shfl_sync(FULL, (k & 1) ? d1 : d0, k >> 1);
        float2 w = wp[k * 32 + lane];
        du.x = fmaf(dk, w.x, du.x);
        du.y = fmaf(dk, w.y, du.y);
    }

    // ---- pairwise interactions (15 upper-tri pairs of 6 features) ----
    float2 f[6];
    f[0] = fu; f[1] = fi; f[2] = fb; f[3] = cv; f[4] = tv; f[5] = du;

    float keep = 0.f;
    int p = 0;
    #pragma unroll
    for (int a = 0; a < 6; a++) {
        #pragma unroll
        for (int b = a + 1; b < 6; b++) {
            float dv = f[a].x * f[b].x + f[a].y * f[b].y;
            #pragma unroll
            for (int off = 16; off > 0; off >>= 1)
                dv += __shfl_xor_sync(FULL, dv, off);
            if (lane == p) keep = dv;
            p++;
        }
    }

    // ---- write transposed x: [inter(15); dense(64)] ----
    if (lane < 15) g_xT[lane * BB + s] = keep;
    g_xT[(15 + 2 * lane) * BB + s] = d0;
    g_xT[(16 + 2 * lane) * BB + s] = d1;
}

// ---------------------------------------------------------------------------
// Kernel 2: top MLP, FFMA2, 128 blocks x 1024 threads (8 j-groups x 128
// samples). Stage A: single tile of 16 neurons/thread (one x pass),
// fully unrolled k-loop with immediate-offset LDS addressing.
// Stage B: 8 outputs/thread, fully unrolled; layer3 + sigmoid.
// ---------------------------------------------------------------------------
#define KP1 40                       // ceil(79/2) k-pairs for layer 1
#define OFF_W1P 0                    // u64[KP1][128]
#define OFF_XP  (OFF_W1P + KP1*128*8)        // u64[KP1][128]
#define OFF_W2P (OFF_XP  + KP1*128*8)        // u64[64][64]
#define OFF_H1P (OFF_W2P + 64*64*8)          // u64[64][128]
#define OFF_B1  (OFF_H1P + 64*128*8)         // float[128]
#define OFF_B2  (OFF_B1 + 128*4)             // float[64]
#define OFF_W3  (OFF_B2 + 64*4)              // float[64]
#define OFF_B3  (OFF_W3 + 64*4)              // float[4]
#define OFF_PZ  (OFF_B3 + 16)                // float[8][128]
#define SMEM_BYTES (OFF_PZ + 8*128*4)

__global__ __launch_bounds__(1024) void top_kernel(
    const float* __restrict__ W1, const float* __restrict__ b1,
    const float* __restrict__ W2, const float* __restrict__ b2,
    const float* __restrict__ W3, const float* __restrict__ b3,
    float* __restrict__ out)
{
    extern __shared__ __align__(16) char sm[];
    u64*   sW1p = (u64*)(sm + OFF_W1P);
    u64*   sXp  = (u64*)(sm + OFF_XP);
    u64*   sW2p = (u64*)(sm + OFF_W2P);
    u64*   sH1p = (u64*)(sm + OFF_H1P);
    float* sb1  = (float*)(sm + OFF_B1);
    float* sb2  = (float*)(sm + OFF_B2);
    float* sW3  = (float*)(sm + OFF_W3);
    float* sb3  = (float*)(sm + OFF_B3);
    float* sPz  = (float*)(sm + OFF_PZ);

    const int tid = threadIdx.x;
    const int sl  = tid & 127;     // sample slot
    const int jg  = tid >> 7;      // group 0..7
    const int S0  = blockIdx.x * 128;

    // ---- stage weights (k-paired even/odd) and x ----
    for (int idx = tid; idx < KP1 * 128; idx += 1024) {
        int t = idx >> 7, j = idx & 127;
        float lo = W1[(2 * t) * 128 + j];
        float hi = (2 * t + 1 < NTOPIN) ? W1[(2 * t + 1) * 128 + j] : 0.f;
        sW1p[idx] = pack2(lo, hi);
    }
    for (int idx = tid; idx < KP1 * 128; idx += 1024) {
        int t = idx >> 7, ss = idx & 127;
        float lo = g_xT[(2 * t) * BB + S0 + ss];
        float hi = (2 * t + 1 < NTOPIN) ? g_xT[(2 * t + 1) * BB + S0 + ss] : 0.f;
        sXp[idx] = pack2(lo, hi);
    }
    for (int idx = tid; idx < 64 * 64; idx += 1024) {
        int t = idx >> 6, m = idx & 63;
        sW2p[idx] = pack2(W2[(2 * t) * 64 + m], W2[(2 * t + 1) * 64 + m]);
    }
    if (tid < 128) sb1[tid] = b1[tid];
    if (tid < 64) { sb2[tid] = b2[tid]; sW3[tid] = W3[tid]; }
    if (tid == 0) sb3[0] = b3[0];
    __syncthreads();

    // ---- stage A: single tile of 16 neurons per thread ----
    {
        const int jbase = jg * 16;
        u64 acc[16];
        #pragma unroll
        for (int r = 0; r < 16; r++) acc[r] = pack2(sb1[jbase + r], 0.f);

        const u64* xcol = sXp + sl;
        const ulonglong2* wrow = (const ulonglong2*)(sW1p + jbase);

        #pragma unroll
        for (int t = 0; t < KP1; t++) {
            u64 x2 = xcol[t * 128];
            #pragma unroll
            for (int r = 0; r < 8; r++) {
                ulonglong2 w = wrow[t * 64 + r];
                ffma2(acc[2 * r],     x2, w.x);
                ffma2(acc[2 * r + 1], x2, w.y);
            }
        }
        // relu(lo+hi), store as pairs into H1p[jp][sl]
        #pragma unroll
        for (int r = 0; r < 16; r += 2) {
            float2 a0 = unpack2(acc[r]);
            float2 a1 = unpack2(acc[r + 1]);
            float h0 = fmaxf(a0.x + a0.y, 0.f);
            float h1 = fmaxf(a1.x + a1.y, 0.f);
            sH1p[((jbase + r) >> 1) * 128 + sl] = pack2(h0, h1);
        }
    }
    __syncthreads();

    // ---- stage B: 8 h2-outputs per thread ----
    const int mbase = jg * 8;
    u64 acc[8];
    #pragma unroll
    for (int r = 0; r < 8; r++) acc[r] = pack2(sb2[mbase + r], 0.f);

    {
        const u64* hcol = sH1p + sl;
        const ulonglong2* wrow = (const ulonglong2*)(sW2p + mbase);
        #pragma unroll
        for (int t = 0; t < 64; t++) {
            u64 h2v = hcol[t * 128];
            #pragma unroll
            for (int r = 0; r < 4; r++) {
                ulonglong2 w = wrow[t * 32 + r];
                ffma2(acc[2 * r],     h2v, w.x);
                ffma2(acc[2 * r + 1], h2v, w.y);
            }
        }
    }

    // ---- layer 3 partial + cross-group reduction + sigmoid ----
    float z = 0.f;
    #pragma unroll
    for (int r = 0; r < 8; r++) {
        float2 a = unpack2(acc[r]);
        float h2 = fmaxf(a.x + a.y, 0.f);
        z = fmaf(h2, sW3[mbase + r], z);
    }
    sPz[jg * 128 + sl] = z;
    __syncthreads();
    if (jg == 0) {
        float zz = sb3[0];
        #pragma unroll
        for (int g = 0; g < 8; g++) zz += sPz[g * 128 + sl];
        out[S0 + sl] = 1.f / (1.f + __expf(-zz));
    }
}

// ---------------------------------------------------------------------------
extern "C" void kernel_launch(void* const* d_in, const int* in_sizes, int n_in,
                              void* d_out, int out_size)
{
    const int*   user       = (const int*)  d_in[0];
    const int*   item       = (const int*)  d_in[1];
    const int*   brand_idx  = (const int*)  d_in[2];
    const int*   cat_idx    = (const int*)  d_in[3];
    const int*   cat_len    = (const int*)  d_in[4];
    const int*   text_idx   = (const int*)  d_in[5];
    const int*   text_len   = (const int*)  d_in[6];
    const float* sales_rank = (const float*)d_in[7];
    const float* user_tab   = (const float*)d_in[8];
    const float* item_tab   = (const float*)d_in[9];
    const float* brand_tab  = (const float*)d_in[10];
    const float* cat_tab    = (const float*)d_in[11];
    const float* text_tab   = (const float*)d_in[12];
    const float* W_bot      = (const float*)d_in[13];
    const float* b_bot      = (const float*)d_in[14];
    const float* W_proj     = (const float*)d_in[15];
    const float* b_proj     = (const float*)d_in[16];
    const float* W_t1       = (const float*)d_in[17];
    const float* b_t1       = (const float*)d_in[18];
    const float* W_t2       = (const float*)d_in[19];
    const float* b_t2       = (const float*)d_in[20];
    const float* W_t3       = (const float*)d_in[21];
    const float* b_t3       = (const float*)d_in[22];
    float* out = (float*)d_out;

    cudaFuncSetAttribute(top_kernel,
                         cudaFuncAttributeMaxDynamicSharedMemorySize,
                         SMEM_BYTES);

    // Kernel 1: warp per sample -> 16384 warps = 2048 blocks x 256 threads
    feat_kernel<<<BB / 8, 256>>>(
        user, item, brand_idx, cat_idx, cat_len, text_idx, text_len,
        sales_rank, user_tab, item_tab, brand_tab, cat_tab, text_tab,
        W_bot, b_bot, W_proj, b_proj);

    // Kernel 2: 128 blocks x 1024 threads, 128 samples per block
    top_kernel<<<128, 1024, SMEM_BYTES>>>(
        W_t1, b_t1, W_t2, b_t2, W_t3, b_t3, out);
}

// round 6
// speedup vs baseline: 1.7924x; 1.0009x over previous
#include <cuda_runtime.h>
#include <cuda_bf16.h>
#include <cstdint>

#define BB 16384
#define DD 64
#define LCAT 8
#define LTXT 64
#define NTOPIN 79
#define NT1 128
#define NT2 64

typedef unsigned long long u64;

// Transposed intermediate: xT[k][s], k in [0,79), s in [0,B)
__device__ float g_xT[NTOPIN * BB];

__device__ __forceinline__ uint32_t smem_u32(const void* p) {
    uint32_t a;
    asm("{ .reg .u64 t; cvta.to.shared.u64 t, %1; cvt.u32.u64 %0, t; }"
        : "=r"(a) : "l"(p));
    return a;
}
__device__ __forceinline__ void ldsm_x4(uint32_t addr, uint32_t* r) {
    asm volatile("ldmatrix.sync.aligned.m8n8.x4.shared.b16 {%0,%1,%2,%3}, [%4];"
        : "=r"(r[0]), "=r"(r[1]), "=r"(r[2]), "=r"(r[3]) : "r"(addr));
}
__device__ __forceinline__ void mma_bf16(float* d, const uint32_t* a,
                                         uint32_t b0, uint32_t b1) {
    asm volatile("mma.sync.aligned.m16n8k16.row.col.f32.bf16.bf16.f32 "
        "{%0,%1,%2,%3}, {%4,%5,%6,%7}, {%8,%9}, {%0,%1,%2,%3};"
        : "+f"(d[0]), "+f"(d[1]), "+f"(d[2]), "+f"(d[3])
        : "r"(a[0]), "r"(a[1]), "r"(a[2]), "r"(a[3]), "r"(b0), "r"(b1));
}
// bf16 hi/lo split: v ~= hi + lo (~16 mantissa bits total)
__device__ __forceinline__ void bsplit(float v, __nv_bfloat16& h, __nv_bfloat16& l) {
    h = __float2bfloat16(v);
    l = __float2bfloat16(v - __bfloat162float(h));
}
__device__ __forceinline__ void bsplit2(float v0, float v1,
                                        __nv_bfloat162& ph, __nv_bfloat162& pl) {
    __nv_bfloat16 h0, l0, h1, l1;
    bsplit(v0, h0, l0); bsplit(v1, h1, l1);
    ph.x = h0; ph.y = h1; pl.x = l0; pl.y = l1;
}

// ---------------------------------------------------------------------------
// Kernel 1: warp-per-sample. Gathers, mean-bags, bottom MLP, projection,
// pairwise interactions. Writes xT (transposed) for kernel 2.
// ---------------------------------------------------------------------------
__global__ __launch_bounds__(256) void feat_kernel(
    const int* __restrict__ user, const int* __restrict__ item,
    const int* __restrict__ brand, const int* __restrict__ cat_idx,
    const int* __restrict__ cat_len, const int* __restrict__ text_idx,
    const int* __restrict__ text_len, const float* __restrict__ sales_rank,
    const float* __restrict__ user_tab, const float* __restrict__ item_tab,
    const float* __restrict__ brand_tab, const float* __restrict__ cat_tab,
    const float* __restrict__ text_tab,
    const float* __restrict__ W_bot, const float* __restrict__ b_bot,
    const float* __restrict__ W_proj, const float* __restrict__ b_proj)
{
    const unsigned FULL = 0xFFFFFFFFu;
    int gwarp = (blockIdx.x * blockDim.x + threadIdx.x) >> 5;
    int lane  = threadIdx.x & 31;
    if (gwarp >= BB) return;
    const int s = gwarp;

    const float2* ut = (const float2*)user_tab;
    const float2* it = (const float2*)item_tab;
    const float2* bt = (const float2*)brand_tab;
    const float4* ct4 = (const float4*)cat_tab;
    const float4* tt4 = (const float4*)text_tab;

    const int sub = lane >> 4;
    const int q   = lane & 15;

    int ui = user[s];
    int ii = item[s];
    int bi = brand[s];
    float2 fu = __ldcs(ut + (size_t)ui * 32 + lane);
    float2 fi = __ldcs(it + (size_t)ii * 32 + lane);
    float2 fb = bt[(size_t)bi * 32 + lane];

    int clen = cat_len[s];
    int tlen = text_len[s];
    int creg = (lane < LCAT) ? cat_idx[s * LCAT + lane] : 0;
    int t0 = text_idx[s * LTXT + lane];
    int t1 = text_idx[s * LTXT + 32 + lane];

    float4 cacc = make_float4(0.f, 0.f, 0.f, 0.f);
    #pragma unroll
    for (int i = 0; i < LCAT; i += 2) {
        int r = i + sub;
        int idx = __shfl_sync(FULL, creg, r);
        if (r < clen) {
            float4 v = ct4[(size_t)idx * 16 + q];
            cacc.x += v.x; cacc.y += v.y; cacc.z += v.z; cacc.w += v.w;
        }
    }

    float4 tacc = make_float4(0.f, 0.f, 0.f, 0.f);
    #pragma unroll
    for (int i = 0; i < LTXT; i += 2) {
        int r = i + sub;
        int idx = __shfl_sync(FULL, (i < 32) ? t0 : t1, r & 31);
        if (r < tlen) {
            float4 v = tt4[(size_t)idx * 16 + q];
            tacc.x += v.x; tacc.y += v.y; tacc.z += v.z; tacc.w += v.w;
        }
    }

    {
        float cinv = 1.f / (float)max(clen, 1);
        float tinv = 1.f / (float)max(tlen, 1);
        cacc.x = (cacc.x + __shfl_down_sync(FULL, cacc.x, 16)) * cinv;
        cacc.y = (cacc.y + __shfl_down_sync(FULL, cacc.y, 16)) * cinv;
        cacc.z = (cacc.z + __shfl_down_sync(FULL, cacc.z, 16)) * cinv;
        cacc.w = (cacc.w + __shfl_down_sync(FULL, cacc.w, 16)) * cinv;
        tacc.x = (tacc.x + __shfl_down_sync(FULL, tacc.x, 16)) * tinv;
        tacc.y = (tacc.y + __shfl_down_sync(FULL, tacc.y, 16)) * tinv;
        tacc.z = (tacc.z + __shfl_down_sync(FULL, tacc.z, 16)) * tinv;
        tacc.w = (tacc.w + __shfl_down_sync(FULL, tacc.w, 16)) * tinv;
    }

    float2 cv, tv;
    {
        int src = lane >> 1;
        float cx = __shfl_sync(FULL, cacc.x, src);
        float cy = __shfl_sync(FULL, cacc.y, src);
        float cz = __shfl_sync(FULL, cacc.z, src);
        float cw = __shfl_sync(FULL, cacc.w, src);
        float tx = __shfl_sync(FULL, tacc.x, src);
        float ty = __shfl_sync(FULL, tacc.y, src);
        float tz = __shfl_sync(FULL, tacc.z, src);
        float tw = __shfl_sync(FULL, tacc.w, src);
        if (lane & 1) { cv = make_float2(cz, cw); tv = make_float2(tz, tw); }
        else          { cv = make_float2(cx, cy); tv = make_float2(tx, ty); }
    }

    float sr = sales_rank[s];
    float d0 = fmaxf(fmaf(sr, W_bot[2 * lane],     b_bot[2 * lane]),     0.f);
    float d1 = fmaxf(fmaf(sr, W_bot[2 * lane + 1], b_bot[2 * lane + 1]), 0.f);

    const float2* wp = (const float2*)W_proj;
    float2 du = make_float2(b_proj[2 * lane], b_proj[2 * lane + 1]);
    #pragma unroll
    for (int k = 0; k < DD; k++) {
        float dk = __shfl_sync(FULL, (k & 1) ? d1 : d0, k >> 1);
        float2 w = wp[k * 32 + lane];
        du.x = fmaf(dk, w.x, du.x);
        du.y = fmaf(dk, w.y, du.y);
    }

    float2 f[6];
    f[0] = fu; f[1] = fi; f[2] = fb; f[3] = cv; f[4] = tv; f[5] = du;

    float keep = 0.f;
    int p = 0;
    #pragma unroll
    for (int a = 0; a < 6; a++) {
        #pragma unroll
        for (int b = a + 1; b < 6; b++) {
            float dv = f[a].x * f[b].x + f[a].y * f[b].y;
            #pragma unroll
            for (int off = 16; off > 0; off >>= 1)
                dv += __shfl_xor_sync(FULL, dv, off);
            if (lane == p) keep = dv;
            p++;
        }
    }

    if (lane < 15) g_xT[lane * BB + s] = keep;
    g_xT[(15 + 2 * lane) * BB + s] = d0;
    g_xT[(16 + 2 * lane) * BB + s] = d1;
}

// ---------------------------------------------------------------------------
// Kernel 2: top MLP via mma.sync bf16 (hi/lo split, 3 terms).
// CTA = 128 samples, 1024 threads (32 warps). All tiles K-major in smem.
// L1: D1[128x128] = X[128x80] @ W1T; relu+bias -> H1 split (reuses A region).
// L2: D2[128x64] = H1[128x128] @ W2T; relu+bias -> sH2; L3 dot + sigmoid.
// ---------------------------------------------------------------------------
#define ASTR   272    // A region row stride bytes (136 bf16)
#define B1STR  176    // W1T row stride bytes (88 bf16)
#define W2STR  272
#define H2STR  66     // floats

#define OFF_AHI   0
#define OFF_ALO   (OFF_AHI + 128 * ASTR)        // 34816
#define OFF_B1HI  (OFF_ALO + 128 * ASTR)        // 69632
#define OFF_B1LO  (OFF_B1HI + 128 * B1STR)      // 92160
#define OFF_W2HI  (OFF_B1LO + 128 * B1STR)      // 114688
#define OFF_W2LO  (OFF_W2HI + 64 * W2STR)       // 132096
#define OFF_SH2   (OFF_W2LO + 64 * W2STR)       // 149504
#define OFF_SB1   (OFF_SH2 + 128 * H2STR * 4)   // 183296
#define OFF_SB2   (OFF_SB1 + 512)
#define OFF_SW3   (OFF_SB2 + 256)
#define OFF_SB3   (OFF_SW3 + 256)
#define TOP_SMEM  (OFF_SB3 + 16)

__global__ __launch_bounds__(1024) void top_mma(
    const float* __restrict__ W1, const float* __restrict__ b1,
    const float* __restrict__ W2, const float* __restrict__ b2,
    const float* __restrict__ W3, const float* __restrict__ b3,
    float* __restrict__ out)
{
    extern __shared__ __align__(16) char sm[];
    const uint32_t smb = smem_u32(sm);
    const int tid = threadIdx.x;
    const int wid = tid >> 5;
    const int lane = tid & 31;
    const int S0 = blockIdx.x * 128;

    float* sb1 = (float*)(sm + OFF_SB1);
    float* sb2 = (float*)(sm + OFF_SB2);
    float* sW3 = (float*)(sm + OFF_SW3);
    float* sb3 = (float*)(sm + OFF_SB3);
    float* sH2 = (float*)(sm + OFF_SH2);

    // ---- stage A = X [row=sample][k<80], hi/lo, K-major ----
    for (int idx = tid; idx < 128 * 40; idx += 1024) {
        int row = idx & 127, k0 = (idx >> 7) * 2;
        float v0 = (k0     < NTOPIN) ? g_xT[(size_t)k0 * BB + S0 + row]       : 0.f;
        float v1 = (k0 + 1 < NTOPIN) ? g_xT[(size_t)(k0 + 1) * BB + S0 + row] : 0.f;
        __nv_bfloat162 ph, pl;
        bsplit2(v0, v1, ph, pl);
        *(__nv_bfloat162*)(sm + OFF_AHI + row * ASTR + k0 * 2) = ph;
        *(__nv_bfloat162*)(sm + OFF_ALO + row * ASTR + k0 * 2) = pl;
    }
    // ---- stage B1 = W1^T [j][k<80] ----
    for (int idx = tid; idx < 128 * 40; idx += 1024) {
        int j = idx & 127, k0 = (idx >> 7) * 2;
        float v0 = (k0     < NTOPIN) ? W1[k0 * 128 + j]       : 0.f;
        float v1 = (k0 + 1 < NTOPIN) ? W1[(k0 + 1) * 128 + j] : 0.f;
        __nv_bfloat162 ph, pl;
        bsplit2(v0, v1, ph, pl);
        *(__nv_bfloat162*)(sm + OFF_B1HI + j * B1STR + k0 * 2) = ph;
        *(__nv_bfloat162*)(sm + OFF_B1LO + j * B1STR + k0 * 2) = pl;
    }
    // ---- stage W2T [m<64][k<128] ----
    for (int idx = tid; idx < 64 * 64; idx += 1024) {
        int m = idx & 63, k0 = (idx >> 6) * 2;
        float v0 = W2[k0 * 64 + m];
        float v1 = W2[(k0 + 1) * 64 + m];
        __nv_bfloat162 ph, pl;
        bsplit2(v0, v1, ph, pl);
        *(__nv_bfloat162*)(sm + OFF_W2HI + m * W2STR + k0 * 2) = ph;
        *(__nv_bfloat162*)(sm + OFF_W2LO + m * W2STR + k0 * 2) = pl;
    }
    if (tid < 128) sb1[tid] = b1[tid];
    if (tid < 64) { sb2[tid] = b2[tid]; sW3[tid] = W3[tid]; }
    if (tid == 0) sb3[0] = b3[0];
    __syncthreads();

    // ================= layer 1 =================
    const int mt  = wid >> 2;          // M-tile (16 rows)
    const int ntb = (wid & 3) * 32;    // 4 N-tiles of 8
    float acc[4][4];
    #pragma unroll
    for (int i = 0; i < 4; i++)
        #pragma unroll
        for (int j = 0; j < 4; j++) acc[i][j] = 0.f;

    const uint32_t a_lane_off = (mt * 16 + (lane & 15)) * ASTR + ((lane >> 4) * 8) * 2;
    const uint32_t b_row = (lane & 7) + ((lane >> 4) & 1) * 8;
    const uint32_t b_k8  = ((lane >> 3) & 1) * 8;

    #pragma unroll
    for (int term = 0; term < 3; term++) {
        uint32_t abase = smb + ((term == 2) ? OFF_ALO : OFF_AHI);
        uint32_t bbase = smb + ((term == 1) ? OFF_B1LO : OFF_B1HI);
        #pragma unroll
        for (int ks = 0; ks < 5; ks++) {
            int k0 = ks * 16;
            uint32_t af[4];
            ldsm_x4(abase + a_lane_off + k0 * 2, af);
            #pragma unroll
            for (int half = 0; half < 2; half++) {
                uint32_t bf[4];
                int n0 = ntb + half * 16;
                ldsm_x4(bbase + (n0 + b_row) * B1STR + (k0 + b_k8) * 2, bf);
                mma_bf16(acc[half * 2],     af, bf[0], bf[1]);
                mma_bf16(acc[half * 2 + 1], af, bf[2], bf[3]);
            }
        }
    }
    __syncthreads();   // everyone done reading A before H1 overwrites it

    // ---- epilogue 1: h1 = relu(D1 + b1) -> hi/lo into A region ----
    {
        int r0 = mt * 16 + (lane >> 2);
        #pragma unroll
        for (int nt = 0; nt < 4; nt++) {
            int c = ntb + nt * 8 + 2 * (lane & 3);
            float h0a = fmaxf(acc[nt][0] + sb1[c],     0.f);
            float h1a = fmaxf(acc[nt][1] + sb1[c + 1], 0.f);
            float h0b = fmaxf(acc[nt][2] + sb1[c],     0.f);
            float h1b = fmaxf(acc[nt][3] + sb1[c + 1], 0.f);
            __nv_bfloat162 ph, pl;
            bsplit2(h0a, h1a, ph, pl);
            *(__nv_bfloat162*)(sm + OFF_AHI + r0 * ASTR + c * 2) = ph;
            *(__nv_bfloat162*)(sm + OFF_ALO + r0 * ASTR + c * 2) = pl;
            bsplit2(h0b, h1b, ph, pl);
            *(__nv_bfloat162*)(sm + OFF_AHI + (r0 + 8) * ASTR + c * 2) = ph;
            *(__nv_bfloat162*)(sm + OFF_ALO + (r0 + 8) * ASTR + c * 2) = pl;
        }
    }
    __syncthreads();

    // ================= layer 2 =================
    const int n0 = (wid & 3) * 16;     // 2 N-tiles of 8
    float acc2[2][4];
    #pragma unroll
    for (int i = 0; i < 2; i++)
        #pragma unroll
        for (int j = 0; j < 4; j++) acc2[i][j] = 0.f;

    #pragma unroll
    for (int term = 0; term < 3; term++) {
        uint32_t abase = smb + ((term == 2) ? OFF_ALO : OFF_AHI);
        uint32_t bbase = smb + ((term == 1) ? OFF_W2LO : OFF_W2HI);
        #pragma unroll
        for (int ks = 0; ks < 8; ks++) {
            int k0 = ks * 16;
            uint32_t af[4];
            ldsm_x4(abase + a_lane_off + k0 * 2, af);
            uint32_t bf[4];
            ldsm_x4(bbase + (n0 + b_row) * W2STR + (k0 + b_k8) * 2, bf);
            mma_bf16(acc2[0], af, bf[0], bf[1]);
            mma_bf16(acc2[1], af, bf[2], bf[3]);
        }
    }

    // ---- epilogue 2: h2 = relu(D2 + b2) -> sH2 ----
    {
        int r0 = mt * 16 + (lane >> 2);
        #pragma unroll
        for (int nt = 0; nt < 2; nt++) {
            int c = n0 + nt * 8 + 2 * (lane & 3);
            float2 va, vb;
            va.x = fmaxf(acc2[nt][0] + sb2[c],     0.f);
            va.y = fmaxf(acc2[nt][1] + sb2[c + 1], 0.f);
            vb.x = fmaxf(acc2[nt][2] + sb2[c],     0.f);
            vb.y = fmaxf(acc2[nt][3] + sb2[c + 1], 0.f);
            *(float2*)(sH2 + r0 * H2STR + c) = va;
            *(float2*)(sH2 + (r0 + 8) * H2STR + c) = vb;
        }
    }
    __syncthreads();

    // ---- layer 3 + sigmoid ----
    if (tid < 128) {
        const float* hrow = sH2 + tid * H2STR;
        float z = sb3[0];
        #pragma unroll
        for (int c = 0; c < 64; c++) z = fmaf(hrow[c], sW3[c], z);
        out[S0 + tid] = 1.f / (1.f + __expf(-z));
    }
}

// ---------------------------------------------------------------------------
extern "C" void kernel_launch(void* const* d_in, const int* in_sizes, int n_in,
                              void* d_out, int out_size)
{
    const int*   user       = (const int*)  d_in[0];
    const int*   item       = (const int*)  d_in[1];
    const int*   brand_idx  = (const int*)  d_in[2];
    const int*   cat_idx    = (const int*)  d_in[3];
    const int*   cat_len    = (const int*)  d_in[4];
    const int*   text_idx   = (const int*)  d_in[5];
    const int*   text_len   = (const int*)  d_in[6];
    const float* sales_rank = (const float*)d_in[7];
    const float* user_tab   = (const float*)d_in[8];
    const float* item_tab   = (const float*)d_in[9];
    const float* brand_tab  = (const float*)d_in[10];
    const float* cat_tab    = (const float*)d_in[11];
    const float* text_tab   = (const float*)d_in[12];
    const float* W_bot      = (const float*)d_in[13];
    const float* b_bot      = (const float*)d_in[14];
    const float* W_proj     = (const float*)d_in[15];
    const float* b_proj     = (const float*)d_in[16];
    const float* W_t1       = (const float*)d_in[17];
    const float* b_t1       = (const float*)d_in[18];
    const float* W_t2       = (const float*)d_in[19];
    const float* b_t2       = (const float*)d_in[20];
    const float* W_t3       = (const float*)d_in[21];
    const float* b_t3       = (const float*)d_in[22];
    float* out = (float*)d_out;

    cudaFuncSetAttribute(top_mma,
                         cudaFuncAttributeMaxDynamicSharedMemorySize,
                         TOP_SMEM);

    feat_kernel<<<BB / 8, 256>>>(
        user, item, brand_idx, cat_idx, cat_len, text_idx, text_len,
        sales_rank, user_tab, item_tab, brand_tab, cat_tab, text_tab,
        W_bot, b_bot, W_proj, b_proj);

    top_mma<<<BB / 128, 1024, TOP_SMEM>>>(
        W_t1, b_t1, W_t2, b_t2, W_t3, b_t3, out);
}

// round 7
// speedup vs baseline: 2.0842x; 1.1628x over previous
#include <cuda_runtime.h>
#include <cuda_bf16.h>
#include <cstdint>

#define BB 16384
#define DD 64
#define LCAT 8
#define LTXT 64
#define NTOPIN 79
#define NT1 128
#define NT2 64

typedef unsigned long long u64;

// Transposed intermediate: xT[k][s], k in [0,79), s in [0,B)
__device__ float g_xT[NTOPIN * BB];

__device__ __forceinline__ uint32_t smem_u32(const void* p) {
    uint32_t a;
    asm("{ .reg .u64 t; cvta.to.shared.u64 t, %1; cvt.u32.u64 %0, t; }"
        : "=r"(a) : "l"(p));
    return a;
}
__device__ __forceinline__ void ldsm_x4(uint32_t addr, uint32_t* r) {
    asm volatile("ldmatrix.sync.aligned.m8n8.x4.shared.b16 {%0,%1,%2,%3}, [%4];"
        : "=r"(r[0]), "=r"(r[1]), "=r"(r[2]), "=r"(r[3]) : "r"(addr));
}
__device__ __forceinline__ void mma_bf16(float* d, const uint32_t* a,
                                         uint32_t b0, uint32_t b1) {
    asm volatile("mma.sync.aligned.m16n8k16.row.col.f32.bf16.bf16.f32 "
        "{%0,%1,%2,%3}, {%4,%5,%6,%7}, {%8,%9}, {%0,%1,%2,%3};"
        : "+f"(d[0]), "+f"(d[1]), "+f"(d[2]), "+f"(d[3])
        : "r"(a[0]), "r"(a[1]), "r"(a[2]), "r"(a[3]), "r"(b0), "r"(b1));
}
// bf16 hi/lo split: v ~= hi + lo (~16 mantissa bits total)
__device__ __forceinline__ void bsplit(float v, __nv_bfloat16& h, __nv_bfloat16& l) {
    h = __float2bfloat16(v);
    l = __float2bfloat16(v - __bfloat162float(h));
}
__device__ __forceinline__ void bsplit2(float v0, float v1,
                                        __nv_bfloat162& ph, __nv_bfloat162& pl) {
    __nv_bfloat16 h0, l0, h1, l1;
    bsplit(v0, h0, l0); bsplit(v1, h1, l1);
    ph.x = h0; ph.y = h1; pl.x = l0; pl.y = l1;
}

// ---------------------------------------------------------------------------
// Kernel 1: warp-per-sample. Gathers, mean-bags, bottom MLP, projection,
// pairwise interactions. Writes xT (transposed) for kernel 2.
// text_tab via __ldcs (256MB, evict-first); cat_tab cached (1.3MB, L2-hit).
// ---------------------------------------------------------------------------
__global__ __launch_bounds__(256) void feat_kernel(
    const int* __restrict__ user, const int* __restrict__ item,
    const int* __restrict__ brand, const int* __restrict__ cat_idx,
    const int* __restrict__ cat_len, const int* __restrict__ text_idx,
    const int* __restrict__ text_len, const float* __restrict__ sales_rank,
    const float* __restrict__ user_tab, const float* __restrict__ item_tab,
    const float* __restrict__ brand_tab, const float* __restrict__ cat_tab,
    const float* __restrict__ text_tab,
    const float* __restrict__ W_bot, const float* __restrict__ b_bot,
    const float* __restrict__ W_proj, const float* __restrict__ b_proj)
{
    const unsigned FULL = 0xFFFFFFFFu;
    int gwarp = (blockIdx.x * blockDim.x + threadIdx.x) >> 5;
    int lane  = threadIdx.x & 31;
    if (gwarp >= BB) return;
    const int s = gwarp;

    const float2* ut = (const float2*)user_tab;
    const float2* it = (const float2*)item_tab;
    const float2* bt = (const float2*)brand_tab;
    const float4* ct4 = (const float4*)cat_tab;
    const float4* tt4 = (const float4*)text_tab;

    const int sub = lane >> 4;
    const int q   = lane & 15;

    int ui = user[s];
    int ii = item[s];
    int bi = brand[s];
    float2 fu = __ldcs(ut + (size_t)ui * 32 + lane);
    float2 fi = __ldcs(it + (size_t)ii * 32 + lane);
    float2 fb = bt[(size_t)bi * 32 + lane];

    int clen = cat_len[s];
    int tlen = text_len[s];
    int creg = (lane < LCAT) ? cat_idx[s * LCAT + lane] : 0;
    int t0 = text_idx[s * LTXT + lane];
    int t1 = text_idx[s * LTXT + 32 + lane];

    float4 cacc = make_float4(0.f, 0.f, 0.f, 0.f);
    #pragma unroll
    for (int i = 0; i < LCAT; i += 2) {
        int r = i + sub;
        int idx = __shfl_sync(FULL, creg, r);
        if (r < clen) {
            float4 v = ct4[(size_t)idx * 16 + q];
            cacc.x += v.x; cacc.y += v.y; cacc.z += v.z; cacc.w += v.w;
        }
    }

    float4 tacc = make_float4(0.f, 0.f, 0.f, 0.f);
    #pragma unroll
    for (int i = 0; i < LTXT; i += 2) {
        int r = i + sub;
        int idx = __shfl_sync(FULL, (i < 32) ? t0 : t1, r & 31);
        if (r < tlen) {
            float4 v = __ldcs(tt4 + (size_t)idx * 16 + q);
            tacc.x += v.x; tacc.y += v.y; tacc.z += v.z; tacc.w += v.w;
        }
    }

    {
        float cinv = 1.f / (float)max(clen, 1);
        float tinv = 1.f / (float)max(tlen, 1);
        cacc.x = (cacc.x + __shfl_down_sync(FULL, cacc.x, 16)) * cinv;
        cacc.y = (cacc.y + __shfl_down_sync(FULL, cacc.y, 16)) * cinv;
        cacc.z = (cacc.z + __shfl_down_sync(FULL, cacc.z, 16)) * cinv;
        cacc.w = (cacc.w + __shfl_down_sync(FULL, cacc.w, 16)) * cinv;
        tacc.x = (tacc.x + __shfl_down_sync(FULL, tacc.x, 16)) * tinv;
        tacc.y = (tacc.y + __shfl_down_sync(FULL, tacc.y, 16)) * tinv;
        tacc.z = (tacc.z + __shfl_down_sync(FULL, tacc.z, 16)) * tinv;
        tacc.w = (tacc.w + __shfl_down_sync(FULL, tacc.w, 16)) * tinv;
    }

    float2 cv, tv;
    {
        int src = lane >> 1;
        float cx = __shfl_sync(FULL, cacc.x, src);
        float cy = __shfl_sync(FULL, cacc.y, src);
        float cz = __shfl_sync(FULL, cacc.z, src);
        float cw = __shfl_sync(FULL, cacc.w, src);
        float tx = __shfl_sync(FULL, tacc.x, src);
        float ty = __shfl_sync(FULL, tacc.y, src);
        float tz = __shfl_sync(FULL, tacc.z, src);
        float tw = __shfl_sync(FULL, tacc.w, src);
        if (lane & 1) { cv = make_float2(cz, cw); tv = make_float2(tz, tw); }
        else          { cv = make_float2(cx, cy); tv = make_float2(tx, ty); }
    }

    float sr = sales_rank[s];
    float d0 = fmaxf(fmaf(sr, W_bot[2 * lane],     b_bot[2 * lane]),     0.f);
    float d1 = fmaxf(fmaf(sr, W_bot[2 * lane + 1], b_bot[2 * lane + 1]), 0.f);

    const float2* wp = (const float2*)W_proj;
    float2 du = make_float2(b_proj[2 * lane], b_proj[2 * lane + 1]);
    #pragma unroll
    for (int k = 0; k < DD; k++) {
        float dk = __shfl_sync(FULL, (k & 1) ? d1 : d0, k >> 1);
        float2 w = wp[k * 32 + lane];
        du.x = fmaf(dk, w.x, du.x);
        du.y = fmaf(dk, w.y, du.y);
    }

    float2 f[6];
    f[0] = fu; f[1] = fi; f[2] = fb; f[3] = cv; f[4] = tv; f[5] = du;

    float keep = 0.f;
    int p = 0;
    #pragma unroll
    for (int a = 0; a < 6; a++) {
        #pragma unroll
        for (int b = a + 1; b < 6; b++) {
            float dv = f[a].x * f[b].x + f[a].y * f[b].y;
            #pragma unroll
            for (int off = 16; off > 0; off >>= 1)
                dv += __shfl_xor_sync(FULL, dv, off);
            if (lane == p) keep = dv;
            p++;
        }
    }

    if (lane < 15) g_xT[lane * BB + s] = keep;
    g_xT[(15 + 2 * lane) * BB + s] = d0;
    g_xT[(16 + 2 * lane) * BB + s] = d1;
}

// ---------------------------------------------------------------------------
// Kernel 2: top MLP via mma.sync bf16 (hi/lo split, 3 terms).
// CTA = 128 samples, 1024 threads (32 warps). All tiles K-major in smem.
// Staging of A and B1 merged into one loop (4 independent global loads/iter).
// ---------------------------------------------------------------------------
#define ASTR   272    // A region row stride bytes (136 bf16)
#define B1STR  176    // W1T row stride bytes (88 bf16)
#define W2STR  272
#define H2STR  66     // floats

#define OFF_AHI   0
#define OFF_ALO   (OFF_AHI + 128 * ASTR)        // 34816
#define OFF_B1HI  (OFF_ALO + 128 * ASTR)        // 69632
#define OFF_B1LO  (OFF_B1HI + 128 * B1STR)      // 92160
#define OFF_W2HI  (OFF_B1LO + 128 * B1STR)      // 114688
#define OFF_W2LO  (OFF_W2HI + 64 * W2STR)       // 132096
#define OFF_SH2   (OFF_W2LO + 64 * W2STR)       // 149504
#define OFF_SB1   (OFF_SH2 + 128 * H2STR * 4)   // 183296
#define OFF_SB2   (OFF_SB1 + 512)
#define OFF_SW3   (OFF_SB2 + 256)
#define OFF_SB3   (OFF_SW3 + 256)
#define TOP_SMEM  (OFF_SB3 + 16)

__global__ __launch_bounds__(1024) void top_mma(
    const float* __restrict__ W1, const float* __restrict__ b1,
    const float* __restrict__ W2, const float* __restrict__ b2,
    const float* __restrict__ W3, const float* __restrict__ b3,
    float* __restrict__ out)
{
    extern __shared__ __align__(16) char sm[];
    const uint32_t smb = smem_u32(sm);
    const int tid = threadIdx.x;
    const int wid = tid >> 5;
    const int lane = tid & 31;
    const int S0 = blockIdx.x * 128;

    float* sb1 = (float*)(sm + OFF_SB1);
    float* sb2 = (float*)(sm + OFF_SB2);
    float* sW3 = (float*)(sm + OFF_SW3);
    float* sb3 = (float*)(sm + OFF_SB3);
    float* sH2 = (float*)(sm + OFF_SH2);

    // ---- merged staging: A = X[row][k<80] and B1 = W1^T[j][k<80], hi/lo ----
    for (int idx = tid; idx < 128 * 40; idx += 1024) {
        int row = idx & 127, k0 = (idx >> 7) * 2;
        bool in0 = (k0 < NTOPIN), in1 = (k0 + 1 < NTOPIN);
        float xv0 = in0 ? g_xT[(size_t)k0 * BB + S0 + row]       : 0.f;
        float xv1 = in1 ? g_xT[(size_t)(k0 + 1) * BB + S0 + row] : 0.f;
        float wv0 = in0 ? W1[k0 * 128 + row]       : 0.f;
        float wv1 = in1 ? W1[(k0 + 1) * 128 + row] : 0.f;
        __nv_bfloat162 ph, pl;
        bsplit2(xv0, xv1, ph, pl);
        *(__nv_bfloat162*)(sm + OFF_AHI + row * ASTR + k0 * 2) = ph;
        *(__nv_bfloat162*)(sm + OFF_ALO + row * ASTR + k0 * 2) = pl;
        bsplit2(wv0, wv1, ph, pl);
        *(__nv_bfloat162*)(sm + OFF_B1HI + row * B1STR + k0 * 2) = ph;
        *(__nv_bfloat162*)(sm + OFF_B1LO + row * B1STR + k0 * 2) = pl;
    }
    // ---- stage W2T [m<64][k<128] ----
    for (int idx = tid; idx < 64 * 64; idx += 1024) {
        int m = idx & 63, k0 = (idx >> 6) * 2;
        float v0 = W2[k0 * 64 + m];
        float v1 = W2[(k0 + 1) * 64 + m];
        __nv_bfloat162 ph, pl;
        bsplit2(v0, v1, ph, pl);
        *(__nv_bfloat162*)(sm + OFF_W2HI + m * W2STR + k0 * 2) = ph;
        *(__nv_bfloat162*)(sm + OFF_W2LO + m * W2STR + k0 * 2) = pl;
    }
    if (tid < 128) sb1[tid] = b1[tid];
    if (tid < 64) { sb2[tid] = b2[tid]; sW3[tid] = W3[tid]; }
    if (tid == 0) sb3[0] = b3[0];
    __syncthreads();

    // ================= layer 1 =================
    const int mt  = wid >> 2;          // M-tile (16 rows)
    const int ntb = (wid & 3) * 32;    // 4 N-tiles of 8
    float acc[4][4];
    #pragma unroll
    for (int i = 0; i < 4; i++)
        #pragma unroll
        for (int j = 0; j < 4; j++) acc[i][j] = 0.f;

    const uint32_t a_lane_off = (mt * 16 + (lane & 15)) * ASTR + ((lane >> 4) * 8) * 2;
    const uint32_t b_row = (lane & 7) + ((lane >> 4) & 1) * 8;
    const uint32_t b_k8  = ((lane >> 3) & 1) * 8;

    #pragma unroll
    for (int term = 0; term < 3; term++) {
        uint32_t abase = smb + ((term == 2) ? OFF_ALO : OFF_AHI);
        uint32_t bbase = smb + ((term == 1) ? OFF_B1LO : OFF_B1HI);
        #pragma unroll
        for (int ks = 0; ks < 5; ks++) {
            int k0 = ks * 16;
            uint32_t af[4];
            ldsm_x4(abase + a_lane_off + k0 * 2, af);
            #pragma unroll
            for (int half = 0; half < 2; half++) {
                uint32_t bf[4];
                int n0 = ntb + half * 16;
                ldsm_x4(bbase + (n0 + b_row) * B1STR + (k0 + b_k8) * 2, bf);
                mma_bf16(acc[half * 2],     af, bf[0], bf[1]);
                mma_bf16(acc[half * 2 + 1], af, bf[2], bf[3]);
            }
        }
    }
    __syncthreads();   // everyone done reading A before H1 overwrites it

    // ---- epilogue 1: h1 = relu(D1 + b1) -> hi/lo into A region ----
    {
        int r0 = mt * 16 + (lane >> 2);
        #pragma unroll
        for (int nt = 0; nt < 4; nt++) {
            int c = ntb + nt * 8 + 2 * (lane & 3);
            float h0a = fmaxf(acc[nt][0] + sb1[c],     0.f);
            float h1a = fmaxf(acc[nt][1] + sb1[c + 1], 0.f);
            float h0b = fmaxf(acc[nt][2] + sb1[c],     0.f);
            float h1b = fmaxf(acc[nt][3] + sb1[c + 1], 0.f);
            __nv_bfloat162 ph, pl;
            bsplit2(h0a, h1a, ph, pl);
            *(__nv_bfloat162*)(sm + OFF_AHI + r0 * ASTR + c * 2) = ph;
            *(__nv_bfloat162*)(sm + OFF_ALO + r0 * ASTR + c * 2) = pl;
            bsplit2(h0b, h1b, ph, pl);
            *(__nv_bfloat162*)(sm + OFF_AHI + (r0 + 8) * ASTR + c * 2) = ph;
            *(__nv_bfloat162*)(sm + OFF_ALO + (r0 + 8) * ASTR + c * 2) = pl;
        }
    }
    __syncthreads();

    // ================= layer 2 =================
    const int n0 = (wid & 3) * 16;     // 2 N-tiles of 8
    float acc2[2][4];
    #pragma unroll
    for (int i = 0; i < 2; i++)
        #pragma unroll
        for (int j = 0; j < 4; j++) acc2[i][j] = 0.f;

    #pragma unroll
    for (int term = 0; term < 3; term++) {
        uint32_t abase = smb + ((term == 2) ? OFF_ALO : OFF_AHI);
        uint32_t bbase = smb + ((term == 1) ? OFF_W2LO : OFF_W2HI);
        #pragma unroll
        for (int ks = 0; ks < 8; ks++) {
            int k0 = ks * 16;
            uint32_t af[4];
            ldsm_x4(abase + a_lane_off + k0 * 2, af);
            uint32_t bf[4];
            ldsm_x4(bbase + (n0 + b_row) * W2STR + (k0 + b_k8) * 2, bf);
            mma_bf16(acc2[0], af, bf[0], bf[1]);
            mma_bf16(acc2[1], af, bf[2], bf[3]);
        }
    }

    // ---- epilogue 2: h2 = relu(D2 + b2) -> sH2 ----
    {
        int r0 = mt * 16 + (lane >> 2);
        #pragma unroll
        for (int nt = 0; nt < 2; nt++) {
            int c = n0 + nt * 8 + 2 * (lane & 3);
            float2 va, vb;
            va.x = fmaxf(acc2[nt][0] + sb2[c],     0.f);
            va.y = fmaxf(acc2[nt][1] + sb2[c + 1], 0.f);
            vb.x = fmaxf(acc2[nt][2] + sb2[c],     0.f);
            vb.y = fmaxf(acc2[nt][3] + sb2[c + 1], 0.f);
            *(float2*)(sH2 + r0 * H2STR + c) = va;
            *(float2*)(sH2 + (r0 + 8) * H2STR + c) = vb;
        }
    }
    __syncthreads();

    // ---- layer 3 + sigmoid ----
    if (tid < 128) {
        const float* hrow = sH2 + tid * H2STR;
        float z = sb3[0];
        #pragma unroll
        for (int c = 0; c < 64; c++) z = fmaf(hrow[c], sW3[c], z);
        out[S0 + tid] = 1.f / (1.f + __expf(-z));
    }
}

// ---------------------------------------------------------------------------
extern "C" void kernel_launch(void* const* d_in, const int* in_sizes, int n_in,
                              void* d_out, int out_size)
{
    const int*   user       = (const int*)  d_in[0];
    const int*   item       = (const int*)  d_in[1];
    const int*   brand_idx  = (const int*)  d_in[2];
    const int*   cat_idx    = (const int*)  d_in[3];
    const int*   cat_len    = (const int*)  d_in[4];
    const int*   text_idx   = (const int*)  d_in[5];
    const int*   text_len   = (const int*)  d_in[6];
    const float* sales_rank = (const float*)d_in[7];
    const float* user_tab   = (const float*)d_in[8];
    const float* item_tab   = (const float*)d_in[9];
    const float* brand_tab  = (const float*)d_in[10];
    const float* cat_tab    = (const float*)d_in[11];
    const float* text_tab   = (const float*)d_in[12];
    const float* W_bot      = (const float*)d_in[13];
    const float* b_bot      = (const float*)d_in[14];
    const float* W_proj     = (const float*)d_in[15];
    const float* b_proj     = (const float*)d_in[16];
    const float* W_t1       = (const float*)d_in[17];
    const float* b_t1       = (const float*)d_in[18];
    const float* W_t2       = (const float*)d_in[19];
    const float* b_t2       = (const float*)d_in[20];
    const float* W_t3       = (const float*)d_in[21];
    const float* b_t3       = (const float*)d_in[22];
    float* out = (float*)d_out;

    cudaFuncSetAttribute(top_mma,
                         cudaFuncAttributeMaxDynamicSharedMemorySize,
                         TOP_SMEM);

    feat_kernel<<<BB / 8, 256>>>(
        user, item, brand_idx, cat_idx, cat_len, text_idx, text_len,
        sales_rank, user_tab, item_tab, brand_tab, cat_tab, text_tab,
        W_bot, b_bot, W_proj, b_proj);

    top_mma<<<BB / 128, 1024, TOP_SMEM>>>(
        W_t1, b_t1, W_t2, b_t2, W_t3, b_t3, out);
}